// round 9
// baseline (speedup 1.0000x reference)
#include <cuda_runtime.h>
#include <cstdint>
#include <math.h>

// ---------------- Problem constants ----------------
constexpr int Bb   = 8;
constexpr int Dd   = 60;
constexpr int NP   = 1024;
constexpr int KNN  = 20;
constexpr int P    = Bb * NP;        // 8192 points
constexpr int M4   = P * KNN;        // 163840 graph-feature rows
constexpr float EPSV  = 1e-5f;
constexpr float SLOPE = 0.2f;

#define NEG_INF (__int_as_float(0xff800000))

// ---------------- packed f32x2 helpers ----------------
__device__ __forceinline__ unsigned long long pack2b(float v) {
    unsigned long long r;
    asm("mov.b64 %0, {%1, %1};" : "=l"(r) : "f"(v));
    return r;
}
__device__ __forceinline__ void ffma2(unsigned long long& d, unsigned long long a,
                                      unsigned long long b) {
    asm("fma.rn.f32x2 %0, %1, %2, %0;" : "+l"(d) : "l"(a), "l"(b));
}
__device__ __forceinline__ void unpack2(unsigned long long p, float& lo, float& hi) {
    asm("mov.b64 {%0, %1}, %2;" : "=f"(lo), "=f"(hi) : "l"(p));
}
// exact float max via atomics (order-independent => deterministic)
__device__ __forceinline__ void amax_f(float* a, float v) {
    if (v >= 0.f) atomicMax((int*)a, __float_as_int(v));
    else          atomicMin((unsigned int*)a, __float_as_uint(v));
}

// ---------------- Device scratch ----------------
__device__ float g_xx[P];
__device__ float g_pd[(size_t)Bb * NP * NP];           // 32 MB
__device__ int   g_idx[M4];
__device__ float g_q[(size_t)P * 64];
__device__ float g_p[(size_t)P * 64];
__device__ float g_t1[(size_t)M4 * 64];
__device__ float g_t2[(size_t)M4 * 64];
__device__ float g_t3[(size_t)M4 * 128];
__device__ float g_cat[(size_t)P * 512];               // RAW per-point maxes
__device__ float g_t5[(size_t)P * 256];
__device__ float g_t6[(size_t)P * 1024];
__device__ float g_ps[1 << 20];
__device__ float g_pq[1 << 20];
__device__ float g_sc[6][1024];
__device__ float g_sh[6][1024];
__device__ float g_csc[512];
__device__ float g_csh[512];

// ---------------- init cat to -inf ----------------
__global__ void init_cat(float* __restrict__ cat) {
    cat[blockIdx.x * 256 + threadIdx.x] = NEG_INF;
}

// ---------------- xx[b,n] = sum_d x^2 ----------------
__global__ void xx_kernel(const float* __restrict__ x) {
    int i = blockIdx.x * 256 + threadIdx.x;
    int b = i >> 10, n = i & 1023;
    const float* xb = x + (size_t)b * Dd * NP + n;
    float s = 0.f;
#pragma unroll
    for (int d = 0; d < Dd; d++) { float v = xb[d * NP]; s += v * v; }
    g_xx[i] = s;
}

// ---------------- pd[b,n,m] = 2*dot - xx_n - xx_m ----------------
__global__ void pd_kernel(const float* __restrict__ x) {
    int b  = blockIdx.z;
    int n0 = blockIdx.y * 64;
    int m0 = blockIdx.x * 64;
    __shared__ float Xa[Dd][64];
    __shared__ float Xb[Dd][64];
    const float* xb = x + (size_t)b * Dd * NP;
    for (int l = threadIdx.x; l < Dd * 64; l += 256) {
        int d = l >> 6, mm = l & 63;
        Xa[d][mm] = xb[d * NP + n0 + mm];
        Xb[d][mm] = xb[d * NP + m0 + mm];
    }
    __syncthreads();
    int tx = threadIdx.x & 15, ty = threadIdx.x >> 4;
    float acc[4][4] = {};
#pragma unroll
    for (int d = 0; d < Dd; d++) {
        float a[4], c[4];
#pragma unroll
        for (int i = 0; i < 4; i++) a[i] = Xa[d][ty * 4 + i];
#pragma unroll
        for (int j = 0; j < 4; j++) c[j] = Xb[d][tx * 4 + j];
#pragma unroll
        for (int i = 0; i < 4; i++)
#pragma unroll
            for (int j = 0; j < 4; j++) acc[i][j] += a[i] * c[j];
    }
#pragma unroll
    for (int i = 0; i < 4; i++) {
        int n = n0 + ty * 4 + i;
        float xn = g_xx[b * NP + n];
#pragma unroll
        for (int j = 0; j < 4; j++) {
            int m = m0 + tx * 4 + j;
            g_pd[((size_t)b << 20) + (size_t)n * NP + m] =
                2.f * acc[i][j] - xn - g_xx[b * NP + m];
        }
    }
}

// ---------------- warp-per-row top-k (k=20), barrier-free ----------------
__global__ __launch_bounds__(512) void topk_kernel() {
    int warp = threadIdx.x >> 5, lane = threadIdx.x & 31;
    int bn = blockIdx.x * 16 + warp;
    const float* row = g_pd + (size_t)bn * NP;
    float v[32];
#pragma unroll
    for (int j = 0; j < 32; j++) v[j] = row[j * 32 + lane];
    float bv = v[0]; int bs = 0;
#pragma unroll
    for (int j = 1; j < 32; j++)
        if (v[j] > bv) { bv = v[j]; bs = j; }
    int* out = g_idx + bn * KNN;
    for (int it = 0; it < KNN; it++) {
        float rv = bv;
        int   ri = bs * 32 + lane;
#pragma unroll
        for (int off = 16; off > 0; off >>= 1) {
            float ov = __shfl_xor_sync(0xffffffffu, rv, off);
            int   oi = __shfl_xor_sync(0xffffffffu, ri, off);
            if (ov > rv || (ov == rv && oi < ri)) { rv = ov; ri = oi; }
        }
        if (lane == 0) out[it] = ri;
        if ((ri & 31) == lane) {
            v[ri >> 5] = NEG_INF;
            bv = v[0]; bs = 0;
#pragma unroll
            for (int j = 1; j < 32; j++)
                if (v[j] > bv) { bv = v[j]; bs = j; }
        }
    }
}

// ---------------- q = A@x, p = (B-A)@x ----------------
__global__ void qp_kernel(const float* __restrict__ x, const float* __restrict__ w1) {
    int b  = blockIdx.y;
    int m0 = blockIdx.x * 64;
    __shared__ float xs[Dd][64];
    __shared__ float ws[64][120];
    const float* xb = x + (size_t)b * Dd * NP;
    for (int l = threadIdx.x; l < Dd * 64; l += 256) {
        int d = l >> 6, m = l & 63;
        xs[d][m] = xb[d * NP + m0 + m];
    }
    for (int l = threadIdx.x; l < 64 * 120; l += 256) ws[l / 120][l % 120] = w1[l];
    __syncthreads();
    int tx = threadIdx.x & 15, ty = threadIdx.x >> 4;
    float qa[4][4] = {}, pa[4][4] = {};
#pragma unroll
    for (int d = 0; d < Dd; d++) {
        float wa[4], wb[4], xm[4];
#pragma unroll
        for (int i = 0; i < 4; i++) {
            wa[i] = ws[ty * 4 + i][d];
            wb[i] = ws[ty * 4 + i][60 + d] - wa[i];
        }
#pragma unroll
        for (int j = 0; j < 4; j++) xm[j] = xs[d][tx * 4 + j];
#pragma unroll
        for (int i = 0; i < 4; i++)
#pragma unroll
            for (int j = 0; j < 4; j++) {
                qa[i][j] += wa[i] * xm[j];
                pa[i][j] += wb[i] * xm[j];
            }
    }
#pragma unroll
    for (int i = 0; i < 4; i++)
#pragma unroll
        for (int j = 0; j < 4; j++) {
            int o = ty * 4 + i, m = m0 + tx * 4 + j;
            size_t base = ((size_t)b * NP + m) * 64 + o;
            g_q[base] = qa[i][j];
            g_p[base] = pa[i][j];
        }
}

// ---------------- s1: gather -> t1, fused stats + x1 raw max ----------------
__global__ __launch_bounds__(256) void s1_kernel(const float* __restrict__ b1,
                                                 float* __restrict__ ps,
                                                 float* __restrict__ pq,
                                                 float* __restrict__ cat) {
    int bn = blockIdx.x;
    int tid = threadIdx.x;
    int c = tid & 63, js = tid >> 6;
    int b = bn >> 10;
    float pv = g_p[(size_t)bn * 64 + c] + b1[c];
    int rbase = bn * KNN;
    float mx = NEG_INF, s = 0.f, q = 0.f;
#pragma unroll
    for (int jj = 0; jj < 5; jj++) {
        int row = rbase + js + jj * 4;
        int m = g_idx[row];
        float v = g_q[((size_t)(b << 10) + m) * 64 + c] + pv;
        g_t1[(size_t)row * 64 + c] = v;
        mx = fmaxf(mx, v); s += v; q += v * v;
    }
    __shared__ float smx[4][64], ssm[4][64], sqm[4][64];
    smx[js][c] = mx; ssm[js][c] = s; sqm[js][c] = q;
    __syncthreads();
    if (js == 0) {
        float M = smx[0][c], S = ssm[0][c], Q = sqm[0][c];
#pragma unroll
        for (int k = 1; k < 4; k++) {
            M = fmaxf(M, smx[k][c]); S += ssm[k][c]; Q += sqm[k][c];
        }
        cat[(size_t)bn * 512 + c] = M;
        ps[(size_t)bn * 64 + c] = S;
        pq[(size_t)bn * 64 + c] = Q;
    }
}

// ---------------- parallel stats finalize ----------------
__global__ void stats_finalize(const float* __restrict__ ps, const float* __restrict__ pq,
                               int nb, int O, float cnt, int stage, int coff,
                               const float* __restrict__ g, const float* __restrict__ be) {
    int c = blockIdx.x * 64 + (threadIdx.x & 63);
    int slot = threadIdx.x >> 6;
    double s = 0.0, q = 0.0;
    for (int i = slot; i < nb; i += 4) {
        s += ps[(size_t)i * O + c];
        q += pq[(size_t)i * O + c];
    }
    __shared__ double ds[4][64], dq[4][64];
    ds[slot][threadIdx.x & 63] = s;
    dq[slot][threadIdx.x & 63] = q;
    __syncthreads();
    if (slot == 0) {
        int t = threadIdx.x & 63;
        double S = ds[0][t], Q = dq[0][t];
#pragma unroll
        for (int k = 1; k < 4; k++) { S += ds[k][t]; Q += dq[k][t]; }
        double m = S / cnt;
        double v = Q / cnt - m * m;
        float a  = g[c] * rsqrtf((float)v + EPSV);
        float sh = be[c] - (float)m * a;
        g_sc[stage][c] = a;
        g_sh[stage][c] = sh;
        if (coff >= 0) { g_csc[coff + c] = a; g_csh[coff + c] = sh; }
    }
}

// =====================================================================
// gemm2: original 8x8-tile FFMA2 GEMM (kept for stage 2, N=64)
// =====================================================================
template <int BM, int BN, bool TRANS, bool WRITE_C, bool MAXF>
__global__ __launch_bounds__(256, 2) void gemm2_kernel(
    const float* __restrict__ A, const float* __restrict__ W,
    const float* __restrict__ bias, const float* __restrict__ tsc,
    const float* __restrict__ tsh, float* __restrict__ C,
    float* __restrict__ ps, float* __restrict__ pq, int K, int NN,
    float* __restrict__ cat, int coff) {
    constexpr int BK = 16;
    constexpr int WM = BM / 64;
    constexpr int WN = BN / 32;
    static_assert(WM * WN == 8, "8 warps");
    constexpr int ALD = BM * BK / (256 * 4);
    constexpr int WLD = BN * BK / (256 * 4);
    constexpr int PTS = BM / 20 + 2;

    __shared__ __align__(16) float As[2][BK][BM + 4];
    __shared__ __align__(16) float Ws[2][BK][BN + 4];
    __shared__ float rs[WM][BN];
    __shared__ float rq[WM][BN];
    __shared__ float smax[MAXF ? PTS : 1][MAXF ? BN : 1];

    int tid  = threadIdx.x;
    int warp = tid >> 5, lane = tid & 31;
    int wm = warp % WM, wn = warp / WM;
    int lm = lane & 7,  ln = lane >> 3;
    int m0 = blockIdx.y * BM;
    int n0 = blockIdx.x * BN;
    int p_base = m0 / KNN;

    if (MAXF) {
        for (int i = tid; i < PTS * BN; i += 256)
            ((float*)smax)[i] = NEG_INF;
    }

    int mb = wm * 64 + lm * 4;
    int nb = wn * 32 + ln * 4;

    float4 apre[ALD], wpre[WLD];
    int r_a[ALD], kq_a[ALD];
#pragma unroll
    for (int u = 0; u < ALD; u++) { int i = tid + 256 * u; r_a[u] = i >> 2; kq_a[u] = i & 3; }
    int r_w[WLD], kq_w[WLD];
#pragma unroll
    for (int u = 0; u < WLD; u++) { int i = tid + 256 * u; r_w[u] = i >> 2; kq_w[u] = i & 3; }

    int tiles = K / BK;
    unsigned long long accp[8][4];
#pragma unroll
    for (int i = 0; i < 8; i++)
#pragma unroll
        for (int jp = 0; jp < 4; jp++) accp[i][jp] = 0ull;

#pragma unroll
    for (int u = 0; u < ALD; u++)
        apre[u] = *(const float4*)(A + (size_t)(m0 + r_a[u]) * K + kq_a[u] * 4);
#pragma unroll
    for (int u = 0; u < WLD; u++)
        wpre[u] = *(const float4*)(W + (size_t)(n0 + r_w[u]) * K + kq_w[u] * 4);
    {
#pragma unroll
        for (int u = 0; u < ALD; u++) {
            float vals[4] = {apre[u].x, apre[u].y, apre[u].z, apre[u].w};
#pragma unroll
            for (int e = 0; e < 4; e++) {
                float v = vals[e];
                if (TRANS) {
                    int kk = kq_a[u] * 4 + e;
                    v = v * tsc[kk] + tsh[kk];
                    v = v >= 0.f ? v : SLOPE * v;
                }
                As[0][kq_a[u] * 4 + e][r_a[u]] = v;
            }
        }
#pragma unroll
        for (int u = 0; u < WLD; u++) {
            Ws[0][kq_w[u] * 4 + 0][r_w[u]] = wpre[u].x;
            Ws[0][kq_w[u] * 4 + 1][r_w[u]] = wpre[u].y;
            Ws[0][kq_w[u] * 4 + 2][r_w[u]] = wpre[u].z;
            Ws[0][kq_w[u] * 4 + 3][r_w[u]] = wpre[u].w;
        }
    }
    __syncthreads();

    for (int t = 0; t < tiles; t++) {
        int cur = t & 1, nxt = cur ^ 1;
        bool has_next = (t + 1) < tiles;
        if (has_next) {
            int k0 = (t + 1) * BK;
#pragma unroll
            for (int u = 0; u < ALD; u++)
                apre[u] = *(const float4*)(A + (size_t)(m0 + r_a[u]) * K + k0 + kq_a[u] * 4);
#pragma unroll
            for (int u = 0; u < WLD; u++)
                wpre[u] = *(const float4*)(W + (size_t)(n0 + r_w[u]) * K + k0 + kq_w[u] * 4);
        }
#pragma unroll
        for (int k = 0; k < BK; k++) {
            float4 a0 = *(const float4*)&As[cur][k][mb];
            float4 a1 = *(const float4*)&As[cur][k][mb + 32];
            ulonglong2 b0 = *(const ulonglong2*)&Ws[cur][k][nb];
            ulonglong2 b1 = *(const ulonglong2*)&Ws[cur][k][nb + 16];
            unsigned long long bp[4] = {b0.x, b0.y, b1.x, b1.y};
            float av[8] = {a0.x, a0.y, a0.z, a0.w, a1.x, a1.y, a1.z, a1.w};
#pragma unroll
            for (int i = 0; i < 8; i++) {
                unsigned long long ap = pack2b(av[i]);
#pragma unroll
                for (int jp = 0; jp < 4; jp++) ffma2(accp[i][jp], ap, bp[jp]);
            }
        }
        if (has_next) {
            int k0 = (t + 1) * BK;
#pragma unroll
            for (int u = 0; u < ALD; u++) {
                float vals[4] = {apre[u].x, apre[u].y, apre[u].z, apre[u].w};
#pragma unroll
                for (int e = 0; e < 4; e++) {
                    float v = vals[e];
                    if (TRANS) {
                        int kk = k0 + kq_a[u] * 4 + e;
                        v = v * tsc[kk] + tsh[kk];
                        v = v >= 0.f ? v : SLOPE * v;
                    }
                    As[nxt][kq_a[u] * 4 + e][r_a[u]] = v;
                }
            }
#pragma unroll
            for (int u = 0; u < WLD; u++) {
                Ws[nxt][kq_w[u] * 4 + 0][r_w[u]] = wpre[u].x;
                Ws[nxt][kq_w[u] * 4 + 1][r_w[u]] = wpre[u].y;
                Ws[nxt][kq_w[u] * 4 + 2][r_w[u]] = wpre[u].z;
                Ws[nxt][kq_w[u] * 4 + 3][r_w[u]] = wpre[u].w;
            }
        }
        __syncthreads();
    }

    float bia[8];
#pragma unroll
    for (int j = 0; j < 8; j++) {
        int n = n0 + nb + (j < 4 ? j : 12 + j);
        bia[j] = bias[n];
    }
    float s_j[8] = {}, q_j[8] = {};
#pragma unroll
    for (int i = 0; i < 8; i++) {
        int mrow = mb + (i < 4 ? i : 28 + i);
        int m = m0 + mrow;
        float vrow[8];
        unpack2(accp[i][0], vrow[0], vrow[1]);
        unpack2(accp[i][1], vrow[2], vrow[3]);
        unpack2(accp[i][2], vrow[4], vrow[5]);
        unpack2(accp[i][3], vrow[6], vrow[7]);
#pragma unroll
        for (int j = 0; j < 8; j++) {
            float v = vrow[j] + bia[j];
            vrow[j] = v;
            s_j[j] += v;
            q_j[j] += v * v;
        }
        if (WRITE_C) {
            *(float4*)(C + (size_t)m * NN + n0 + nb) =
                make_float4(vrow[0], vrow[1], vrow[2], vrow[3]);
            *(float4*)(C + (size_t)m * NN + n0 + nb + 16) =
                make_float4(vrow[4], vrow[5], vrow[6], vrow[7]);
        }
        if (MAXF) {
            int pl = m / KNN - p_base;
#pragma unroll
            for (int j = 0; j < 8; j++) {
                int c = nb + (j < 4 ? j : 12 + j);
                amax_f(&smax[pl][c], vrow[j]);
            }
        }
    }
#pragma unroll
    for (int off = 1; off < 8; off <<= 1) {
#pragma unroll
        for (int j = 0; j < 8; j++) {
            s_j[j] += __shfl_xor_sync(0xffffffffu, s_j[j], off);
            q_j[j] += __shfl_xor_sync(0xffffffffu, q_j[j], off);
        }
    }
    __syncthreads();
    if (lm == 0) {
#pragma unroll
        for (int j = 0; j < 8; j++) {
            int c = nb + (j < 4 ? j : 12 + j);
            rs[wm][c] = s_j[j];
            rq[wm][c] = q_j[j];
        }
    }
    __syncthreads();
    for (int c = tid; c < BN; c += 256) {
        float s = 0.f, q = 0.f;
#pragma unroll
        for (int w = 0; w < WM; w++) { s += rs[w][c]; q += rq[w][c]; }
        ps[(size_t)blockIdx.y * NN + n0 + c] = s;
        pq[(size_t)blockIdx.y * NN + n0 + c] = q;
    }
    if (MAXF) {
        int npts = (m0 + BM - 1) / KNN - p_base + 1;
        for (int idx = tid; idx < npts * BN; idx += 256) {
            int pl = idx / BN, c = idx % BN;
            float v = smax[pl][c];
            if (v > NEG_INF)
                amax_f(&cat[(size_t)(p_base + pl) * 512 + coff + n0 + c], v);
        }
    }
}

// =====================================================================
// gemm3: 8m x 16n thread-tile FFMA2 GEMM (0.75 B/MAC smem -> fma-bound)
//   256 threads, 8 warps (WM x WN), warp tile 64x64
//   BM = 64*WM, BN = 64*WN;  1 block/SM
// =====================================================================
template <int WN, bool TRANS, bool WRITE_C, bool MAXF>
__global__ __launch_bounds__(256, 1) void gemm3_kernel(
    const float* __restrict__ A, const float* __restrict__ W,
    const float* __restrict__ bias, const float* __restrict__ tsc,
    const float* __restrict__ tsh, float* __restrict__ C,
    float* __restrict__ ps, float* __restrict__ pq, int K, int NN,
    float* __restrict__ cat, int coff) {
    constexpr int BK = 16;
    constexpr int WM = 8 / WN;
    constexpr int BM = 64 * WM;
    constexpr int BN = 64 * WN;
    constexpr int ALD = BM * BK / (256 * 4);
    constexpr int WLD = BN * BK / (256 * 4);
    constexpr int PTS = BM / 20 + 2;

    __shared__ __align__(16) float As[2][BK][BM + 4];
    __shared__ __align__(16) float Ws[2][BK][BN + 4];
    __shared__ float rs[WM][BN];
    __shared__ float rq[WM][BN];
    __shared__ float smax[MAXF ? PTS : 1][MAXF ? BN : 1];

    int tid  = threadIdx.x;
    int warp = tid >> 5, lane = tid & 31;
    int wm = warp % WM, wn = warp / WM;
    int lm = lane & 7,  ln = lane >> 3;
    int m0 = blockIdx.y * BM;
    int n0 = blockIdx.x * BN;
    int p_base = m0 / KNN;

    if (MAXF) {
        for (int i = tid; i < PTS * BN; i += 256)
            ((float*)smax)[i] = NEG_INF;
    }

    int mb = wm * 64 + lm * 4;             // m: +{0..3}, +32
    int nb = wn * 64 + ln * 4;             // n: +{0..3}, +16, +32, +48

    float4 apre[ALD], wpre[WLD];
    int r_a[ALD], kq_a[ALD];
#pragma unroll
    for (int u = 0; u < ALD; u++) { int i = tid + 256 * u; r_a[u] = i >> 2; kq_a[u] = i & 3; }
    int r_w[WLD], kq_w[WLD];
#pragma unroll
    for (int u = 0; u < WLD; u++) { int i = tid + 256 * u; r_w[u] = i >> 2; kq_w[u] = i & 3; }

    int tiles = K / BK;
    unsigned long long accp[8][8];
#pragma unroll
    for (int i = 0; i < 8; i++)
#pragma unroll
        for (int jp = 0; jp < 8; jp++) accp[i][jp] = 0ull;

    // prologue: load + store tile 0
#pragma unroll
    for (int u = 0; u < ALD; u++)
        apre[u] = *(const float4*)(A + (size_t)(m0 + r_a[u]) * K + kq_a[u] * 4);
#pragma unroll
    for (int u = 0; u < WLD; u++)
        wpre[u] = *(const float4*)(W + (size_t)(n0 + r_w[u]) * K + kq_w[u] * 4);
    {
#pragma unroll
        for (int u = 0; u < ALD; u++) {
            float vals[4] = {apre[u].x, apre[u].y, apre[u].z, apre[u].w};
#pragma unroll
            for (int e = 0; e < 4; e++) {
                float v = vals[e];
                if (TRANS) {
                    int kk = kq_a[u] * 4 + e;
                    v = v * tsc[kk] + tsh[kk];
                    v = v >= 0.f ? v : SLOPE * v;
                }
                As[0][kq_a[u] * 4 + e][r_a[u]] = v;
            }
        }
#pragma unroll
        for (int u = 0; u < WLD; u++) {
            Ws[0][kq_w[u] * 4 + 0][r_w[u]] = wpre[u].x;
            Ws[0][kq_w[u] * 4 + 1][r_w[u]] = wpre[u].y;
            Ws[0][kq_w[u] * 4 + 2][r_w[u]] = wpre[u].z;
            Ws[0][kq_w[u] * 4 + 3][r_w[u]] = wpre[u].w;
        }
    }
    __syncthreads();

    for (int t = 0; t < tiles; t++) {
        int cur = t & 1, nxt = cur ^ 1;
        bool has_next = (t + 1) < tiles;
        if (has_next) {
            int k0 = (t + 1) * BK;
#pragma unroll
            for (int u = 0; u < ALD; u++)
                apre[u] = *(const float4*)(A + (size_t)(m0 + r_a[u]) * K + k0 + kq_a[u] * 4);
#pragma unroll
            for (int u = 0; u < WLD; u++)
                wpre[u] = *(const float4*)(W + (size_t)(n0 + r_w[u]) * K + k0 + kq_w[u] * 4);
        }
#pragma unroll
        for (int k = 0; k < BK; k++) {
            float4 a0 = *(const float4*)&As[cur][k][mb];
            float4 a1 = *(const float4*)&As[cur][k][mb + 32];
            ulonglong2 b0 = *(const ulonglong2*)&Ws[cur][k][nb];
            ulonglong2 b1 = *(const ulonglong2*)&Ws[cur][k][nb + 16];
            ulonglong2 b2 = *(const ulonglong2*)&Ws[cur][k][nb + 32];
            ulonglong2 b3 = *(const ulonglong2*)&Ws[cur][k][nb + 48];
            unsigned long long bp[8] = {b0.x, b0.y, b1.x, b1.y, b2.x, b2.y, b3.x, b3.y};
            float av[8] = {a0.x, a0.y, a0.z, a0.w, a1.x, a1.y, a1.z, a1.w};
#pragma unroll
            for (int i = 0; i < 8; i++) {
                unsigned long long ap = pack2b(av[i]);
#pragma unroll
                for (int jp = 0; jp < 8; jp++) ffma2(accp[i][jp], ap, bp[jp]);
            }
        }
        if (has_next) {
            int k0 = (t + 1) * BK;
#pragma unroll
            for (int u = 0; u < ALD; u++) {
                float vals[4] = {apre[u].x, apre[u].y, apre[u].z, apre[u].w};
#pragma unroll
                for (int e = 0; e < 4; e++) {
                    float v = vals[e];
                    if (TRANS) {
                        int kk = k0 + kq_a[u] * 4 + e;
                        v = v * tsc[kk] + tsh[kk];
                        v = v >= 0.f ? v : SLOPE * v;
                    }
                    As[nxt][kq_a[u] * 4 + e][r_a[u]] = v;
                }
            }
#pragma unroll
            for (int u = 0; u < WLD; u++) {
                Ws[nxt][kq_w[u] * 4 + 0][r_w[u]] = wpre[u].x;
                Ws[nxt][kq_w[u] * 4 + 1][r_w[u]] = wpre[u].y;
                Ws[nxt][kq_w[u] * 4 + 2][r_w[u]] = wpre[u].z;
                Ws[nxt][kq_w[u] * 4 + 3][r_w[u]] = wpre[u].w;
            }
        }
        __syncthreads();
    }

    // ---- epilogue: bias, (store C), fused stats, (fused raw max) ----
    // n channel of pair jp: nc(jp) = (jp>>1)*16 + (jp&1)*2 (+0/1)
    float bia[16];
#pragma unroll
    for (int jp = 0; jp < 8; jp++) {
        int n = n0 + nb + (jp >> 1) * 16 + (jp & 1) * 2;
        bia[jp * 2]     = bias[n];
        bia[jp * 2 + 1] = bias[n + 1];
    }
    float s_j[16] = {}, q_j[16] = {};
#pragma unroll
    for (int i = 0; i < 8; i++) {
        int mrow = mb + (i < 4 ? i : 28 + i);
        int m = m0 + mrow;
        float vrow[16];
#pragma unroll
        for (int jp = 0; jp < 8; jp++)
            unpack2(accp[i][jp], vrow[jp * 2], vrow[jp * 2 + 1]);
#pragma unroll
        for (int j = 0; j < 16; j++) {
            float v = vrow[j] + bia[j];
            vrow[j] = v;
            s_j[j] += v;
            q_j[j] += v * v;
        }
        if (WRITE_C) {
#pragma unroll
            for (int ch = 0; ch < 4; ch++)
                *(float4*)(C + (size_t)m * NN + n0 + nb + ch * 16) =
                    make_float4(vrow[ch * 4 + 0], vrow[ch * 4 + 1],
                                vrow[ch * 4 + 2], vrow[ch * 4 + 3]);
        }
        if (MAXF) {
            int pl = m / KNN - p_base;
#pragma unroll
            for (int j = 0; j < 16; j++) {
                int c = nb + (j >> 2) * 16 + (j & 3);
                amax_f(&smax[pl][c], vrow[j]);
            }
        }
    }
#pragma unroll
    for (int off = 1; off < 8; off <<= 1) {
#pragma unroll
        for (int j = 0; j < 16; j++) {
            s_j[j] += __shfl_xor_sync(0xffffffffu, s_j[j], off);
            q_j[j] += __shfl_xor_sync(0xffffffffu, q_j[j], off);
        }
    }
    __syncthreads();
    if (lm == 0) {
#pragma unroll
        for (int j = 0; j < 16; j++) {
            int c = nb - wn * 64 + (j >> 2) * 16 + (j & 3) + wn * 64;  // block-local n
            rs[wm][c] = s_j[j];
            rq[wm][c] = q_j[j];
        }
    }
    __syncthreads();
    for (int c = tid; c < BN; c += 256) {
        float s = 0.f, q = 0.f;
#pragma unroll
        for (int w = 0; w < WM; w++) { s += rs[w][c]; q += rq[w][c]; }
        ps[(size_t)blockIdx.y * NN + n0 + c] = s;
        pq[(size_t)blockIdx.y * NN + n0 + c] = q;
    }
    if (MAXF) {
        int npts = (m0 + BM - 1) / KNN - p_base + 1;
        for (int idx = tid; idx < npts * BN; idx += 256) {
            int pl = idx / BN, c = idx % BN;
            float v = smax[pl][c];
            if (v > NEG_INF)
                amax_f(&cat[(size_t)(p_base + pl) * 512 + coff + n0 + c], v);
        }
    }
}

// ---------------- final ----------------
__global__ void final_kernel(float* __restrict__ out) {
    int i = blockIdx.x * 256 + threadIdx.x;
    int c = i & 1023;
    float v = g_sc[5][c] * g_t6[i] + g_sh[5][c];
    out[i] = v >= 0.f ? v : SLOPE * v;
}

// ---------------- launch ----------------
extern "C" void kernel_launch(void* const* d_in, const int* in_sizes, int n_in,
                              void* d_out, int out_size) {
    const float* x  = (const float*)d_in[0];
    const float* w1 = (const float*)d_in[1];
    const float* b1 = (const float*)d_in[2];
    const float* g1 = (const float*)d_in[3];
    const float* be1= (const float*)d_in[4];
    const float* w2 = (const float*)d_in[5];
    const float* b2 = (const float*)d_in[6];
    const float* g2 = (const float*)d_in[7];
    const float* be2= (const float*)d_in[8];
    const float* w3 = (const float*)d_in[9];
    const float* b3 = (const float*)d_in[10];
    const float* g3 = (const float*)d_in[11];
    const float* be3= (const float*)d_in[12];
    const float* w4 = (const float*)d_in[13];
    const float* b4 = (const float*)d_in[14];
    const float* g4 = (const float*)d_in[15];
    const float* be4= (const float*)d_in[16];
    const float* w5 = (const float*)d_in[17];
    const float* b5 = (const float*)d_in[18];
    const float* g5 = (const float*)d_in[19];
    const float* be5= (const float*)d_in[20];
    const float* w6 = (const float*)d_in[21];
    const float* b6 = (const float*)d_in[22];
    const float* g6 = (const float*)d_in[23];
    const float* be6= (const float*)d_in[24];
    float* out = (float*)d_out;

    float *t1, *t2, *t3, *t5, *t6, *cat, *scb, *shb, *csc, *csh, *ps, *pq;
    cudaGetSymbolAddress((void**)&t1, g_t1);
    cudaGetSymbolAddress((void**)&t2, g_t2);
    cudaGetSymbolAddress((void**)&t3, g_t3);
    cudaGetSymbolAddress((void**)&t5, g_t5);
    cudaGetSymbolAddress((void**)&t6, g_t6);
    cudaGetSymbolAddress((void**)&cat, g_cat);
    cudaGetSymbolAddress((void**)&scb, g_sc);
    cudaGetSymbolAddress((void**)&shb, g_sh);
    cudaGetSymbolAddress((void**)&csc, g_csc);
    cudaGetSymbolAddress((void**)&csh, g_csh);
    cudaGetSymbolAddress((void**)&ps, g_ps);
    cudaGetSymbolAddress((void**)&pq, g_pq);

    // init cat to -inf (atomic-max accumulator)
    init_cat<<<P * 512 / 256, 256>>>(cat);

    // KNN
    xx_kernel<<<P / 256, 256>>>(x);
    pd_kernel<<<dim3(16, 16, Bb), 256>>>(x);
    topk_kernel<<<P / 16, 512>>>();

    // Stage 1: decomposed conv + gather; fused stats + x1 raw max
    qp_kernel<<<dim3(16, Bb), 256>>>(x, w1);
    s1_kernel<<<P, 256>>>(b1, ps, pq, cat);
    stats_finalize<<<1, 256>>>(ps, pq, P, 64, (float)M4, 0, 0, g1, be1);

    // Stage 2: t1 -> t2 (BN1+lrelu folded); fused stats + x2 raw max
    gemm2_kernel<256, 64, true, true, true><<<dim3(1, M4 / 256), 256>>>(
        t1, w2, b2, scb + 0 * 1024, shb + 0 * 1024, t2, ps, pq, 64, 64, cat, 64);
    stats_finalize<<<1, 256>>>(ps, pq, M4 / 256, 64, (float)M4, 1, 64, g2, be2);

    // Stage 3: BM=256, BN=128; fused stats + x3 raw max
    gemm3_kernel<2, true, true, true><<<dim3(1, M4 / 256), 256>>>(
        t2, w3, b3, scb + 1 * 1024, shb + 1 * 1024, t3, ps, pq, 64, 128, cat, 128);
    stats_finalize<<<2, 256>>>(ps, pq, M4 / 256, 128, (float)M4, 2, 128, g3, be3);

    // Stage 4: BM=128, BN=256; no C write; fused stats + x4 raw max
    gemm3_kernel<4, true, false, true><<<dim3(1, M4 / 128), 256>>>(
        t3, w4, b4, scb + 2 * 1024, shb + 2 * 1024, nullptr, ps, pq, 128, 256, cat, 256);
    stats_finalize<<<4, 256>>>(ps, pq, M4 / 128, 256, (float)M4, 3, 256, g4, be4);

    // Stage 5: raw cat -> t5, folding four stages' BN+lrelu via csc/csh
    gemm3_kernel<4, true, true, false><<<dim3(1, P / 128), 256>>>(
        cat, w5, b5, csc, csh, t5, ps, pq, 512, 256, nullptr, 0);
    stats_finalize<<<4, 256>>>(ps, pq, P / 128, 256, (float)P, 4, -1, g5, be5);

    // Stage 6: BM=128, BN=256, N=1024 (grid.x=4)
    gemm3_kernel<4, true, true, false><<<dim3(4, P / 128), 256>>>(
        t5, w6, b6, scb + 4 * 1024, shb + 4 * 1024, t6, ps, pq, 256, 1024, nullptr, 0);
    stats_finalize<<<16, 256>>>(ps, pq, P / 128, 1024, (float)P, 5, -1, g6, be6);

    // Final BN+lrelu -> output (B, N, 1024)
    final_kernel<<<P * 1024 / 256, 256>>>(out);
}

// round 10
// speedup vs baseline: 1.1515x; 1.1515x over previous
#include <cuda_runtime.h>
#include <cstdint>
#include <math.h>

// ---------------- Problem constants ----------------
constexpr int Bb   = 8;
constexpr int Dd   = 60;
constexpr int NP   = 1024;
constexpr int KNN  = 20;
constexpr int P    = Bb * NP;        // 8192 points
constexpr int M4   = P * KNN;        // 163840 graph-feature rows
constexpr float EPSV  = 1e-5f;
constexpr float SLOPE = 0.2f;

#define NEG_INF (__int_as_float(0xff800000))

// ---------------- packed f32x2 helpers ----------------
__device__ __forceinline__ unsigned long long pack2b(float v) {
    unsigned long long r;
    asm("mov.b64 %0, {%1, %1};" : "=l"(r) : "f"(v));
    return r;
}
__device__ __forceinline__ void ffma2(unsigned long long& d, unsigned long long a,
                                      unsigned long long b) {
    asm("fma.rn.f32x2 %0, %1, %2, %0;" : "+l"(d) : "l"(a), "l"(b));
}
__device__ __forceinline__ void unpack2(unsigned long long p, float& lo, float& hi) {
    asm("mov.b64 {%0, %1}, %2;" : "=f"(lo), "=f"(hi) : "l"(p));
}
// exact float max via atomics (order-independent => deterministic)
__device__ __forceinline__ void amax_f(float* a, float v) {
    if (v >= 0.f) atomicMax((int*)a, __float_as_int(v));
    else          atomicMin((unsigned int*)a, __float_as_uint(v));
}
// order-preserving float->uint key (monotone): single atomicMax, no divergence
__device__ __forceinline__ unsigned int fenc(float f) {
    unsigned int b = __float_as_uint(f);
    return b ^ ((unsigned int)((int)b >> 31) | 0x80000000u);
}
__device__ __forceinline__ float fdec(unsigned int u) {
    unsigned int b = (u & 0x80000000u) ? (u ^ 0x80000000u) : ~u;
    return __uint_as_float(b);
}

// ---------------- Device scratch ----------------
__device__ float g_xx[P];
__device__ float g_pd[(size_t)Bb * NP * NP];           // 32 MB
__device__ int   g_idx[M4];
__device__ float g_q[(size_t)P * 64];
__device__ float g_p[(size_t)P * 64];
__device__ float g_t1[(size_t)M4 * 64];
__device__ float g_t2[(size_t)M4 * 64];
__device__ float g_t3[(size_t)M4 * 128];
__device__ float g_cat[(size_t)P * 512];               // RAW per-point maxes
__device__ float g_t5[(size_t)P * 256];
__device__ float g_t6[(size_t)P * 1024];
__device__ float g_ps[1 << 20];
__device__ float g_pq[1 << 20];
__device__ float g_sc[6][1024];
__device__ float g_sh[6][1024];
__device__ float g_csc[512];
__device__ float g_csh[512];

// ---------------- init cat to -inf ----------------
__global__ void init_cat(float* __restrict__ cat) {
    cat[blockIdx.x * 256 + threadIdx.x] = NEG_INF;
}

// ---------------- xx[b,n] = sum_d x^2 ----------------
__global__ void xx_kernel(const float* __restrict__ x) {
    int i = blockIdx.x * 256 + threadIdx.x;
    int b = i >> 10, n = i & 1023;
    const float* xb = x + (size_t)b * Dd * NP + n;
    float s = 0.f;
#pragma unroll
    for (int d = 0; d < Dd; d++) { float v = xb[d * NP]; s += v * v; }
    g_xx[i] = s;
}

// ---------------- pd[b,n,m] = 2*dot - xx_n - xx_m ----------------
__global__ void pd_kernel(const float* __restrict__ x) {
    int b  = blockIdx.z;
    int n0 = blockIdx.y * 64;
    int m0 = blockIdx.x * 64;
    __shared__ float Xa[Dd][64];
    __shared__ float Xb[Dd][64];
    const float* xb = x + (size_t)b * Dd * NP;
    for (int l = threadIdx.x; l < Dd * 64; l += 256) {
        int d = l >> 6, mm = l & 63;
        Xa[d][mm] = xb[d * NP + n0 + mm];
        Xb[d][mm] = xb[d * NP + m0 + mm];
    }
    __syncthreads();
    int tx = threadIdx.x & 15, ty = threadIdx.x >> 4;
    float acc[4][4] = {};
#pragma unroll
    for (int d = 0; d < Dd; d++) {
        float a[4], c[4];
#pragma unroll
        for (int i = 0; i < 4; i++) a[i] = Xa[d][ty * 4 + i];
#pragma unroll
        for (int j = 0; j < 4; j++) c[j] = Xb[d][tx * 4 + j];
#pragma unroll
        for (int i = 0; i < 4; i++)
#pragma unroll
            for (int j = 0; j < 4; j++) acc[i][j] += a[i] * c[j];
    }
#pragma unroll
    for (int i = 0; i < 4; i++) {
        int n = n0 + ty * 4 + i;
        float xn = g_xx[b * NP + n];
#pragma unroll
        for (int j = 0; j < 4; j++) {
            int m = m0 + tx * 4 + j;
            g_pd[((size_t)b << 20) + (size_t)n * NP + m] =
                2.f * acc[i][j] - xn - g_xx[b * NP + m];
        }
    }
}

// ---------------- warp-per-row top-k (k=20), barrier-free ----------------
__global__ __launch_bounds__(512) void topk_kernel() {
    int warp = threadIdx.x >> 5, lane = threadIdx.x & 31;
    int bn = blockIdx.x * 16 + warp;
    const float* row = g_pd + (size_t)bn * NP;
    float v[32];
#pragma unroll
    for (int j = 0; j < 32; j++) v[j] = row[j * 32 + lane];
    float bv = v[0]; int bs = 0;
#pragma unroll
    for (int j = 1; j < 32; j++)
        if (v[j] > bv) { bv = v[j]; bs = j; }
    int* out = g_idx + bn * KNN;
    for (int it = 0; it < KNN; it++) {
        float rv = bv;
        int   ri = bs * 32 + lane;
#pragma unroll
        for (int off = 16; off > 0; off >>= 1) {
            float ov = __shfl_xor_sync(0xffffffffu, rv, off);
            int   oi = __shfl_xor_sync(0xffffffffu, ri, off);
            if (ov > rv || (ov == rv && oi < ri)) { rv = ov; ri = oi; }
        }
        if (lane == 0) out[it] = ri;
        if ((ri & 31) == lane) {
            v[ri >> 5] = NEG_INF;
            bv = v[0]; bs = 0;
#pragma unroll
            for (int j = 1; j < 32; j++)
                if (v[j] > bv) { bv = v[j]; bs = j; }
        }
    }
}

// ---------------- q = A@x, p = (B-A)@x ----------------
__global__ void qp_kernel(const float* __restrict__ x, const float* __restrict__ w1) {
    int b  = blockIdx.y;
    int m0 = blockIdx.x * 64;
    __shared__ float xs[Dd][64];
    __shared__ float ws[64][120];
    const float* xb = x + (size_t)b * Dd * NP;
    for (int l = threadIdx.x; l < Dd * 64; l += 256) {
        int d = l >> 6, m = l & 63;
        xs[d][m] = xb[d * NP + m0 + m];
    }
    for (int l = threadIdx.x; l < 64 * 120; l += 256) ws[l / 120][l % 120] = w1[l];
    __syncthreads();
    int tx = threadIdx.x & 15, ty = threadIdx.x >> 4;
    float qa[4][4] = {}, pa[4][4] = {};
#pragma unroll
    for (int d = 0; d < Dd; d++) {
        float wa[4], wb[4], xm[4];
#pragma unroll
        for (int i = 0; i < 4; i++) {
            wa[i] = ws[ty * 4 + i][d];
            wb[i] = ws[ty * 4 + i][60 + d] - wa[i];
        }
#pragma unroll
        for (int j = 0; j < 4; j++) xm[j] = xs[d][tx * 4 + j];
#pragma unroll
        for (int i = 0; i < 4; i++)
#pragma unroll
            for (int j = 0; j < 4; j++) {
                qa[i][j] += wa[i] * xm[j];
                pa[i][j] += wb[i] * xm[j];
            }
    }
#pragma unroll
    for (int i = 0; i < 4; i++)
#pragma unroll
        for (int j = 0; j < 4; j++) {
            int o = ty * 4 + i, m = m0 + tx * 4 + j;
            size_t base = ((size_t)b * NP + m) * 64 + o;
            g_q[base] = qa[i][j];
            g_p[base] = pa[i][j];
        }
}

// ---------------- s1: gather -> t1, fused stats + x1 raw max ----------------
__global__ __launch_bounds__(256) void s1_kernel(const float* __restrict__ b1,
                                                 float* __restrict__ ps,
                                                 float* __restrict__ pq,
                                                 float* __restrict__ cat) {
    int bn = blockIdx.x;
    int tid = threadIdx.x;
    int c = tid & 63, js = tid >> 6;
    int b = bn >> 10;
    float pv = g_p[(size_t)bn * 64 + c] + b1[c];
    int rbase = bn * KNN;
    float mx = NEG_INF, s = 0.f, q = 0.f;
#pragma unroll
    for (int jj = 0; jj < 5; jj++) {
        int row = rbase + js + jj * 4;
        int m = g_idx[row];
        float v = g_q[((size_t)(b << 10) + m) * 64 + c] + pv;
        g_t1[(size_t)row * 64 + c] = v;
        mx = fmaxf(mx, v); s += v; q += v * v;
    }
    __shared__ float smx[4][64], ssm[4][64], sqm[4][64];
    smx[js][c] = mx; ssm[js][c] = s; sqm[js][c] = q;
    __syncthreads();
    if (js == 0) {
        float M = smx[0][c], S = ssm[0][c], Q = sqm[0][c];
#pragma unroll
        for (int k = 1; k < 4; k++) {
            M = fmaxf(M, smx[k][c]); S += ssm[k][c]; Q += sqm[k][c];
        }
        cat[(size_t)bn * 512 + c] = M;
        ps[(size_t)bn * 64 + c] = S;
        pq[(size_t)bn * 64 + c] = Q;
    }
}

// ---------------- parallel stats finalize ----------------
__global__ void stats_finalize(const float* __restrict__ ps, const float* __restrict__ pq,
                               int nb, int O, float cnt, int stage, int coff,
                               const float* __restrict__ g, const float* __restrict__ be) {
    int c = blockIdx.x * 64 + (threadIdx.x & 63);
    int slot = threadIdx.x >> 6;
    double s = 0.0, q = 0.0;
    for (int i = slot; i < nb; i += 4) {
        s += ps[(size_t)i * O + c];
        q += pq[(size_t)i * O + c];
    }
    __shared__ double ds[4][64], dq[4][64];
    ds[slot][threadIdx.x & 63] = s;
    dq[slot][threadIdx.x & 63] = q;
    __syncthreads();
    if (slot == 0) {
        int t = threadIdx.x & 63;
        double S = ds[0][t], Q = dq[0][t];
#pragma unroll
        for (int k = 1; k < 4; k++) { S += ds[k][t]; Q += dq[k][t]; }
        double m = S / cnt;
        double v = Q / cnt - m * m;
        float a  = g[c] * rsqrtf((float)v + EPSV);
        float sh = be[c] - (float)m * a;
        g_sc[stage][c] = a;
        g_sh[stage][c] = sh;
        if (coff >= 0) { g_csc[coff + c] = a; g_csh[coff + c] = sh; }
    }
}

// =====================================================================
// gemm2: 8x8-tile FFMA2 GEMM, double-buffered, fused stats
//   MAXF: per-point raw max; register pre-merge by point id, then ONE
//   encoded uint atomicMax per (point,channel) flush (no divergence)
// =====================================================================
template <int BM, int BN, bool TRANS, bool WRITE_C, bool MAXF>
__global__ __launch_bounds__(256, 2) void gemm2_kernel(
    const float* __restrict__ A, const float* __restrict__ W,
    const float* __restrict__ bias, const float* __restrict__ tsc,
    const float* __restrict__ tsh, float* __restrict__ C,
    float* __restrict__ ps, float* __restrict__ pq, int K, int NN,
    float* __restrict__ cat, int coff) {
    constexpr int BK = 16;
    constexpr int WM = BM / 64;
    constexpr int WN = BN / 32;
    static_assert(WM * WN == 8, "8 warps");
    constexpr int ALD = BM * BK / (256 * 4);
    constexpr int WLD = BN * BK / (256 * 4);
    constexpr int PTS = BM / 20 + 2;

    __shared__ __align__(16) float As[2][BK][BM + 4];
    __shared__ __align__(16) float Ws[2][BK][BN + 4];
    __shared__ float rs[WM][BN];
    __shared__ float rq[WM][BN];
    __shared__ unsigned int smax[MAXF ? PTS : 1][MAXF ? BN : 1];

    int tid  = threadIdx.x;
    int warp = tid >> 5, lane = tid & 31;
    int wm = warp % WM, wn = warp / WM;
    int lm = lane & 7,  ln = lane >> 3;
    int m0 = blockIdx.y * BM;
    int n0 = blockIdx.x * BN;
    int p_base = m0 / KNN;

    if (MAXF) {
        for (int i = tid; i < PTS * BN; i += 256)
            ((unsigned int*)smax)[i] = 0u;             // encoded sentinel (decodes to NaN -> skipped)
    }

    int mb = wm * 64 + lm * 4;
    int nb = wn * 32 + ln * 4;

    float4 apre[ALD], wpre[WLD];
    int r_a[ALD], kq_a[ALD];
#pragma unroll
    for (int u = 0; u < ALD; u++) { int i = tid + 256 * u; r_a[u] = i >> 2; kq_a[u] = i & 3; }
    int r_w[WLD], kq_w[WLD];
#pragma unroll
    for (int u = 0; u < WLD; u++) { int i = tid + 256 * u; r_w[u] = i >> 2; kq_w[u] = i & 3; }

    int tiles = K / BK;
    unsigned long long accp[8][4];
#pragma unroll
    for (int i = 0; i < 8; i++)
#pragma unroll
        for (int jp = 0; jp < 4; jp++) accp[i][jp] = 0ull;

#pragma unroll
    for (int u = 0; u < ALD; u++)
        apre[u] = *(const float4*)(A + (size_t)(m0 + r_a[u]) * K + kq_a[u] * 4);
#pragma unroll
    for (int u = 0; u < WLD; u++)
        wpre[u] = *(const float4*)(W + (size_t)(n0 + r_w[u]) * K + kq_w[u] * 4);
    {
#pragma unroll
        for (int u = 0; u < ALD; u++) {
            float vals[4] = {apre[u].x, apre[u].y, apre[u].z, apre[u].w};
#pragma unroll
            for (int e = 0; e < 4; e++) {
                float v = vals[e];
                if (TRANS) {
                    int kk = kq_a[u] * 4 + e;
                    v = v * tsc[kk] + tsh[kk];
                    v = v >= 0.f ? v : SLOPE * v;
                }
                As[0][kq_a[u] * 4 + e][r_a[u]] = v;
            }
        }
#pragma unroll
        for (int u = 0; u < WLD; u++) {
            Ws[0][kq_w[u] * 4 + 0][r_w[u]] = wpre[u].x;
            Ws[0][kq_w[u] * 4 + 1][r_w[u]] = wpre[u].y;
            Ws[0][kq_w[u] * 4 + 2][r_w[u]] = wpre[u].z;
            Ws[0][kq_w[u] * 4 + 3][r_w[u]] = wpre[u].w;
        }
    }
    __syncthreads();

    for (int t = 0; t < tiles; t++) {
        int cur = t & 1, nxt = cur ^ 1;
        bool has_next = (t + 1) < tiles;
        if (has_next) {
            int k0 = (t + 1) * BK;
#pragma unroll
            for (int u = 0; u < ALD; u++)
                apre[u] = *(const float4*)(A + (size_t)(m0 + r_a[u]) * K + k0 + kq_a[u] * 4);
#pragma unroll
            for (int u = 0; u < WLD; u++)
                wpre[u] = *(const float4*)(W + (size_t)(n0 + r_w[u]) * K + k0 + kq_w[u] * 4);
        }
#pragma unroll
        for (int k = 0; k < BK; k++) {
            float4 a0 = *(const float4*)&As[cur][k][mb];
            float4 a1 = *(const float4*)&As[cur][k][mb + 32];
            ulonglong2 b0 = *(const ulonglong2*)&Ws[cur][k][nb];
            ulonglong2 b1 = *(const ulonglong2*)&Ws[cur][k][nb + 16];
            unsigned long long bp[4] = {b0.x, b0.y, b1.x, b1.y};
            float av[8] = {a0.x, a0.y, a0.z, a0.w, a1.x, a1.y, a1.z, a1.w};
#pragma unroll
            for (int i = 0; i < 8; i++) {
                unsigned long long ap = pack2b(av[i]);
#pragma unroll
                for (int jp = 0; jp < 4; jp++) ffma2(accp[i][jp], ap, bp[jp]);
            }
        }
        if (has_next) {
            int k0 = (t + 1) * BK;
#pragma unroll
            for (int u = 0; u < ALD; u++) {
                float vals[4] = {apre[u].x, apre[u].y, apre[u].z, apre[u].w};
#pragma unroll
                for (int e = 0; e < 4; e++) {
                    float v = vals[e];
                    if (TRANS) {
                        int kk = k0 + kq_a[u] * 4 + e;
                        v = v * tsc[kk] + tsh[kk];
                        v = v >= 0.f ? v : SLOPE * v;
                    }
                    As[nxt][kq_a[u] * 4 + e][r_a[u]] = v;
                }
            }
#pragma unroll
            for (int u = 0; u < WLD; u++) {
                Ws[nxt][kq_w[u] * 4 + 0][r_w[u]] = wpre[u].x;
                Ws[nxt][kq_w[u] * 4 + 1][r_w[u]] = wpre[u].y;
                Ws[nxt][kq_w[u] * 4 + 2][r_w[u]] = wpre[u].z;
                Ws[nxt][kq_w[u] * 4 + 3][r_w[u]] = wpre[u].w;
            }
        }
        __syncthreads();
    }

    // ---- epilogue: bias, (store C), fused stats, (point-merged max) ----
    float bia[8];
#pragma unroll
    for (int j = 0; j < 8; j++) {
        int n = n0 + nb + (j < 4 ? j : 12 + j);
        bia[j] = bias[n];
    }
    float s_j[8] = {}, q_j[8] = {};
    float runmax[8];
    int cur_pl = -1;
#pragma unroll
    for (int i = 0; i < 8; i++) {
        int mrow = mb + (i < 4 ? i : 28 + i);         // ascending m within thread
        int m = m0 + mrow;
        float vrow[8];
        unpack2(accp[i][0], vrow[0], vrow[1]);
        unpack2(accp[i][1], vrow[2], vrow[3]);
        unpack2(accp[i][2], vrow[4], vrow[5]);
        unpack2(accp[i][3], vrow[6], vrow[7]);
#pragma unroll
        for (int j = 0; j < 8; j++) {
            float v = vrow[j] + bia[j];
            vrow[j] = v;
            s_j[j] += v;
            q_j[j] += v * v;
        }
        if (WRITE_C) {
            *(float4*)(C + (size_t)m * NN + n0 + nb) =
                make_float4(vrow[0], vrow[1], vrow[2], vrow[3]);
            *(float4*)(C + (size_t)m * NN + n0 + nb + 16) =
                make_float4(vrow[4], vrow[5], vrow[6], vrow[7]);
        }
        if (MAXF) {
            int pl = m / KNN - p_base;
            if (pl != cur_pl) {
                if (cur_pl >= 0) {
#pragma unroll
                    for (int j = 0; j < 8; j++) {
                        int c = nb + (j < 4 ? j : 12 + j);
                        atomicMax(&smax[cur_pl][c], fenc(runmax[j]));
                    }
                }
                cur_pl = pl;
#pragma unroll
                for (int j = 0; j < 8; j++) runmax[j] = vrow[j];
            } else {
#pragma unroll
                for (int j = 0; j < 8; j++) runmax[j] = fmaxf(runmax[j], vrow[j]);
            }
        }
    }
    if (MAXF && cur_pl >= 0) {
#pragma unroll
        for (int j = 0; j < 8; j++) {
            int c = nb + (j < 4 ? j : 12 + j);
            atomicMax(&smax[cur_pl][c], fenc(runmax[j]));
        }
    }
#pragma unroll
    for (int off = 1; off < 8; off <<= 1) {
#pragma unroll
        for (int j = 0; j < 8; j++) {
            s_j[j] += __shfl_xor_sync(0xffffffffu, s_j[j], off);
            q_j[j] += __shfl_xor_sync(0xffffffffu, q_j[j], off);
        }
    }
    __syncthreads();
    if (lm == 0) {
#pragma unroll
        for (int j = 0; j < 8; j++) {
            int c = nb + (j < 4 ? j : 12 + j);
            rs[wm][c] = s_j[j];
            rq[wm][c] = q_j[j];
        }
    }
    __syncthreads();
    for (int c = tid; c < BN; c += 256) {
        float s = 0.f, q = 0.f;
#pragma unroll
        for (int w = 0; w < WM; w++) { s += rs[w][c]; q += rq[w][c]; }
        ps[(size_t)blockIdx.y * NN + n0 + c] = s;
        pq[(size_t)blockIdx.y * NN + n0 + c] = q;
    }
    if (MAXF) {
        int npts = (m0 + BM - 1) / KNN - p_base + 1;
        for (int idx = tid; idx < npts * BN; idx += 256) {
            int pl = idx / BN, c = idx % BN;
            float v = fdec(smax[pl][c]);
            if (v > NEG_INF)                           // NaN sentinel / -inf skipped
                amax_f(&cat[(size_t)(p_base + pl) * 512 + coff + n0 + c], v);
        }
    }
}

// ---------------- final ----------------
__global__ void final_kernel(float* __restrict__ out) {
    int i = blockIdx.x * 256 + threadIdx.x;
    int c = i & 1023;
    float v = g_sc[5][c] * g_t6[i] + g_sh[5][c];
    out[i] = v >= 0.f ? v : SLOPE * v;
}

// ---------------- launch ----------------
extern "C" void kernel_launch(void* const* d_in, const int* in_sizes, int n_in,
                              void* d_out, int out_size) {
    const float* x  = (const float*)d_in[0];
    const float* w1 = (const float*)d_in[1];
    const float* b1 = (const float*)d_in[2];
    const float* g1 = (const float*)d_in[3];
    const float* be1= (const float*)d_in[4];
    const float* w2 = (const float*)d_in[5];
    const float* b2 = (const float*)d_in[6];
    const float* g2 = (const float*)d_in[7];
    const float* be2= (const float*)d_in[8];
    const float* w3 = (const float*)d_in[9];
    const float* b3 = (const float*)d_in[10];
    const float* g3 = (const float*)d_in[11];
    const float* be3= (const float*)d_in[12];
    const float* w4 = (const float*)d_in[13];
    const float* b4 = (const float*)d_in[14];
    const float* g4 = (const float*)d_in[15];
    const float* be4= (const float*)d_in[16];
    const float* w5 = (const float*)d_in[17];
    const float* b5 = (const float*)d_in[18];
    const float* g5 = (const float*)d_in[19];
    const float* be5= (const float*)d_in[20];
    const float* w6 = (const float*)d_in[21];
    const float* b6 = (const float*)d_in[22];
    const float* g6 = (const float*)d_in[23];
    const float* be6= (const float*)d_in[24];
    float* out = (float*)d_out;

    float *t1, *t2, *t3, *t5, *t6, *cat, *scb, *shb, *csc, *csh, *ps, *pq;
    cudaGetSymbolAddress((void**)&t1, g_t1);
    cudaGetSymbolAddress((void**)&t2, g_t2);
    cudaGetSymbolAddress((void**)&t3, g_t3);
    cudaGetSymbolAddress((void**)&t5, g_t5);
    cudaGetSymbolAddress((void**)&t6, g_t6);
    cudaGetSymbolAddress((void**)&cat, g_cat);
    cudaGetSymbolAddress((void**)&scb, g_sc);
    cudaGetSymbolAddress((void**)&shb, g_sh);
    cudaGetSymbolAddress((void**)&csc, g_csc);
    cudaGetSymbolAddress((void**)&csh, g_csh);
    cudaGetSymbolAddress((void**)&ps, g_ps);
    cudaGetSymbolAddress((void**)&pq, g_pq);

    // init cat to -inf (atomic-max accumulator)
    init_cat<<<P * 512 / 256, 256>>>(cat);

    // KNN
    xx_kernel<<<P / 256, 256>>>(x);
    pd_kernel<<<dim3(16, 16, Bb), 256>>>(x);
    topk_kernel<<<P / 16, 512>>>();

    // Stage 1: decomposed conv + gather; fused stats + x1 raw max
    qp_kernel<<<dim3(16, Bb), 256>>>(x, w1);
    s1_kernel<<<P, 256>>>(b1, ps, pq, cat);
    stats_finalize<<<1, 256>>>(ps, pq, P, 64, (float)M4, 0, 0, g1, be1);

    // Stage 2: t1 -> t2 (BN1+lrelu folded); fused stats + x2 raw max
    gemm2_kernel<256, 64, true, true, true><<<dim3(1, M4 / 256), 256>>>(
        t1, w2, b2, scb + 0 * 1024, shb + 0 * 1024, t2, ps, pq, 64, 64, cat, 64);
    stats_finalize<<<1, 256>>>(ps, pq, M4 / 256, 64, (float)M4, 1, 64, g2, be2);

    // Stage 3: fused stats + x3 raw max
    gemm2_kernel<128, 128, true, true, true><<<dim3(1, M4 / 128), 256>>>(
        t2, w3, b3, scb + 1 * 1024, shb + 1 * 1024, t3, ps, pq, 64, 128, cat, 128);
    stats_finalize<<<2, 256>>>(ps, pq, M4 / 128, 128, (float)M4, 2, 128, g3, be3);

    // Stage 4: no C write; fused stats + x4 raw max
    gemm2_kernel<128, 128, true, false, true><<<dim3(2, M4 / 128), 256>>>(
        t3, w4, b4, scb + 2 * 1024, shb + 2 * 1024, nullptr, ps, pq, 128, 256, cat, 256);
    stats_finalize<<<4, 256>>>(ps, pq, M4 / 128, 256, (float)M4, 3, 256, g4, be4);

    // Stage 5: raw cat -> t5, folding four stages' BN+lrelu via csc/csh
    gemm2_kernel<128, 128, true, true, false><<<dim3(2, P / 128), 256>>>(
        cat, w5, b5, csc, csh, t5, ps, pq, 512, 256, nullptr, 0);
    stats_finalize<<<4, 256>>>(ps, pq, P / 128, 256, (float)P, 4, -1, g5, be5);

    // Stage 6
    gemm2_kernel<128, 128, true, true, false><<<dim3(8, P / 128), 256>>>(
        t5, w6, b6, scb + 4 * 1024, shb + 4 * 1024, t6, ps, pq, 256, 1024, nullptr, 0);
    stats_finalize<<<16, 256>>>(ps, pq, P / 128, 1024, (float)P, 5, -1, g6, be6);

    // Final BN+lrelu -> output (B, N, 1024)
    final_kernel<<<P * 1024 / 256, 256>>>(out);
}

// round 12
// speedup vs baseline: 1.2087x; 1.0496x over previous
#include <cuda_runtime.h>
#include <cuda_bf16.h>
#include <cstdint>
#include <math.h>

// ---------------- Problem constants ----------------
constexpr int Bb   = 8;
constexpr int Dd   = 60;
constexpr int NP   = 1024;
constexpr int KNN  = 20;
constexpr int P    = Bb * NP;        // 8192 points
constexpr int M4   = P * KNN;        // 163840 graph-feature rows
constexpr float EPSV  = 1e-5f;
constexpr float SLOPE = 0.2f;

#define NEG_INF (__int_as_float(0xff800000))

// ---------------- packed f32x2 helpers ----------------
__device__ __forceinline__ unsigned long long pack2b(float v) {
    unsigned long long r;
    asm("mov.b64 %0, {%1, %1};" : "=l"(r) : "f"(v));
    return r;
}
__device__ __forceinline__ void ffma2(unsigned long long& d, unsigned long long a,
                                      unsigned long long b) {
    asm("fma.rn.f32x2 %0, %1, %2, %0;" : "+l"(d) : "l"(a), "l"(b));
}
__device__ __forceinline__ void unpack2(unsigned long long p, float& lo, float& hi) {
    asm("mov.b64 {%0, %1}, %2;" : "=f"(lo), "=f"(hi) : "l"(p));
}
// exact float max via atomics (order-independent => deterministic)
__device__ __forceinline__ void amax_f(float* a, float v) {
    if (v >= 0.f) atomicMax((int*)a, __float_as_int(v));
    else          atomicMin((unsigned int*)a, __float_as_uint(v));
}
// order-preserving float->uint key
__device__ __forceinline__ unsigned int fenc(float f) {
    unsigned int b = __float_as_uint(f);
    return b ^ ((unsigned int)((int)b >> 31) | 0x80000000u);
}
__device__ __forceinline__ float fdec(unsigned int u) {
    unsigned int b = (u & 0x80000000u) ? (u ^ 0x80000000u) : ~u;
    return __uint_as_float(b);
}

// ---------------- mma.sync helpers (sm_80+ PTX, works on plain sm_103) ----
__device__ __forceinline__ uint32_t smem_u32(const void* p) {
    uint32_t a;
    asm("{ .reg .u64 t; cvta.to.shared.u64 t, %1; cvt.u32.u64 %0, t; }" : "=r"(a) : "l"(p));
    return a;
}
__device__ __forceinline__ void ldsm4(uint32_t* r, uint32_t addr) {
    asm volatile("ldmatrix.sync.aligned.m8n8.x4.shared.b16 {%0,%1,%2,%3}, [%4];"
        : "=r"(r[0]), "=r"(r[1]), "=r"(r[2]), "=r"(r[3]) : "r"(addr));
}
__device__ __forceinline__ void mma16816(float* d, const uint32_t* a, const uint32_t* b) {
    asm volatile("mma.sync.aligned.m16n8k16.row.col.f32.bf16.bf16.f32 "
        "{%0,%1,%2,%3}, {%4,%5,%6,%7}, {%8,%9}, {%0,%1,%2,%3};"
        : "+f"(d[0]), "+f"(d[1]), "+f"(d[2]), "+f"(d[3])
        : "r"(a[0]), "r"(a[1]), "r"(a[2]), "r"(a[3]), "r"(b[0]), "r"(b[1]));
}

// ---------------- Device scratch ----------------
__device__ float g_xx[P];
__device__ float g_pd[(size_t)Bb * NP * NP];
__device__ int   g_idx[M4];
__device__ float g_q[(size_t)P * 64];
__device__ float g_p[(size_t)P * 64];
__device__ float g_t1[(size_t)M4 * 64];
__device__ float g_t2[(size_t)M4 * 64];
__device__ float g_t3[(size_t)M4 * 128];
__device__ float g_cat[(size_t)P * 512];
__device__ float g_t5[(size_t)P * 256];
__device__ float g_t6[(size_t)P * 1024];
__device__ float g_ps[1 << 20];
__device__ float g_pq[1 << 20];
__device__ float g_sc[6][1024];
__device__ float g_sh[6][1024];
__device__ float g_csc[512];
__device__ float g_csh[512];
__device__ __nv_bfloat16 g_w4h[256 * 128];
__device__ __nv_bfloat16 g_w4l[256 * 128];

// ---------------- init cat to -inf ----------------
__global__ void init_cat(float* __restrict__ cat) {
    cat[blockIdx.x * 256 + threadIdx.x] = NEG_INF;
}

// ---------------- xx ----------------
__global__ void xx_kernel(const float* __restrict__ x) {
    int i = blockIdx.x * 256 + threadIdx.x;
    int b = i >> 10, n = i & 1023;
    const float* xb = x + (size_t)b * Dd * NP + n;
    float s = 0.f;
#pragma unroll
    for (int d = 0; d < Dd; d++) { float v = xb[d * NP]; s += v * v; }
    g_xx[i] = s;
}

// ---------------- pd ----------------
__global__ void pd_kernel(const float* __restrict__ x) {
    int b  = blockIdx.z;
    int n0 = blockIdx.y * 64;
    int m0 = blockIdx.x * 64;
    __shared__ float Xa[Dd][64];
    __shared__ float Xb[Dd][64];
    const float* xb = x + (size_t)b * Dd * NP;
    for (int l = threadIdx.x; l < Dd * 64; l += 256) {
        int d = l >> 6, mm = l & 63;
        Xa[d][mm] = xb[d * NP + n0 + mm];
        Xb[d][mm] = xb[d * NP + m0 + mm];
    }
    __syncthreads();
    int tx = threadIdx.x & 15, ty = threadIdx.x >> 4;
    float acc[4][4] = {};
#pragma unroll
    for (int d = 0; d < Dd; d++) {
        float a[4], c[4];
#pragma unroll
        for (int i = 0; i < 4; i++) a[i] = Xa[d][ty * 4 + i];
#pragma unroll
        for (int j = 0; j < 4; j++) c[j] = Xb[d][tx * 4 + j];
#pragma unroll
        for (int i = 0; i < 4; i++)
#pragma unroll
            for (int j = 0; j < 4; j++) acc[i][j] += a[i] * c[j];
    }
#pragma unroll
    for (int i = 0; i < 4; i++) {
        int n = n0 + ty * 4 + i;
        float xn = g_xx[b * NP + n];
#pragma unroll
        for (int j = 0; j < 4; j++) {
            int m = m0 + tx * 4 + j;
            g_pd[((size_t)b << 20) + (size_t)n * NP + m] =
                2.f * acc[i][j] - xn - g_xx[b * NP + m];
        }
    }
}

// ---------------- warp-per-row top-k ----------------
__global__ __launch_bounds__(512) void topk_kernel() {
    int warp = threadIdx.x >> 5, lane = threadIdx.x & 31;
    int bn = blockIdx.x * 16 + warp;
    const float* row = g_pd + (size_t)bn * NP;
    float v[32];
#pragma unroll
    for (int j = 0; j < 32; j++) v[j] = row[j * 32 + lane];
    float bv = v[0]; int bs = 0;
#pragma unroll
    for (int j = 1; j < 32; j++)
        if (v[j] > bv) { bv = v[j]; bs = j; }
    int* out = g_idx + bn * KNN;
    for (int it = 0; it < KNN; it++) {
        float rv = bv;
        int   ri = bs * 32 + lane;
#pragma unroll
        for (int off = 16; off > 0; off >>= 1) {
            float ov = __shfl_xor_sync(0xffffffffu, rv, off);
            int   oi = __shfl_xor_sync(0xffffffffu, ri, off);
            if (ov > rv || (ov == rv && oi < ri)) { rv = ov; ri = oi; }
        }
        if (lane == 0) out[it] = ri;
        if ((ri & 31) == lane) {
            v[ri >> 5] = NEG_INF;
            bv = v[0]; bs = 0;
#pragma unroll
            for (int j = 1; j < 32; j++)
                if (v[j] > bv) { bv = v[j]; bs = j; }
        }
    }
}

// ---------------- qp ----------------
__global__ void qp_kernel(const float* __restrict__ x, const float* __restrict__ w1) {
    int b  = blockIdx.y;
    int m0 = blockIdx.x * 64;
    __shared__ float xs[Dd][64];
    __shared__ float ws[64][120];
    const float* xb = x + (size_t)b * Dd * NP;
    for (int l = threadIdx.x; l < Dd * 64; l += 256) {
        int d = l >> 6, m = l & 63;
        xs[d][m] = xb[d * NP + m0 + m];
    }
    for (int l = threadIdx.x; l < 64 * 120; l += 256) ws[l / 120][l % 120] = w1[l];
    __syncthreads();
    int tx = threadIdx.x & 15, ty = threadIdx.x >> 4;
    float qa[4][4] = {}, pa[4][4] = {};
#pragma unroll
    for (int d = 0; d < Dd; d++) {
        float wa[4], wb[4], xm[4];
#pragma unroll
        for (int i = 0; i < 4; i++) {
            wa[i] = ws[ty * 4 + i][d];
            wb[i] = ws[ty * 4 + i][60 + d] - wa[i];
        }
#pragma unroll
        for (int j = 0; j < 4; j++) xm[j] = xs[d][tx * 4 + j];
#pragma unroll
        for (int i = 0; i < 4; i++)
#pragma unroll
            for (int j = 0; j < 4; j++) {
                qa[i][j] += wa[i] * xm[j];
                pa[i][j] += wb[i] * xm[j];
            }
    }
#pragma unroll
    for (int i = 0; i < 4; i++)
#pragma unroll
        for (int j = 0; j < 4; j++) {
            int o = ty * 4 + i, m = m0 + tx * 4 + j;
            size_t base = ((size_t)b * NP + m) * 64 + o;
            g_q[base] = qa[i][j];
            g_p[base] = pa[i][j];
        }
}

// ---------------- s1 ----------------
__global__ __launch_bounds__(256) void s1_kernel(const float* __restrict__ b1,
                                                 float* __restrict__ ps,
                                                 float* __restrict__ pq,
                                                 float* __restrict__ cat) {
    int bn = blockIdx.x;
    int tid = threadIdx.x;
    int c = tid & 63, js = tid >> 6;
    int b = bn >> 10;
    float pv = g_p[(size_t)bn * 64 + c] + b1[c];
    int rbase = bn * KNN;
    float mx = NEG_INF, s = 0.f, q = 0.f;
#pragma unroll
    for (int jj = 0; jj < 5; jj++) {
        int row = rbase + js + jj * 4;
        int m = g_idx[row];
        float v = g_q[((size_t)(b << 10) + m) * 64 + c] + pv;
        g_t1[(size_t)row * 64 + c] = v;
        mx = fmaxf(mx, v); s += v; q += v * v;
    }
    __shared__ float smx[4][64], ssm[4][64], sqm[4][64];
    smx[js][c] = mx; ssm[js][c] = s; sqm[js][c] = q;
    __syncthreads();
    if (js == 0) {
        float M = smx[0][c], S = ssm[0][c], Q = sqm[0][c];
#pragma unroll
        for (int k = 1; k < 4; k++) {
            M = fmaxf(M, smx[k][c]); S += ssm[k][c]; Q += sqm[k][c];
        }
        cat[(size_t)bn * 512 + c] = M;
        ps[(size_t)bn * 64 + c] = S;
        pq[(size_t)bn * 64 + c] = Q;
    }
}

// ---------------- stats finalize ----------------
__global__ void stats_finalize(const float* __restrict__ ps, const float* __restrict__ pq,
                               int nb, int O, float cnt, int stage, int coff,
                               const float* __restrict__ g, const float* __restrict__ be) {
    int c = blockIdx.x * 64 + (threadIdx.x & 63);
    int slot = threadIdx.x >> 6;
    double s = 0.0, q = 0.0;
    for (int i = slot; i < nb; i += 4) {
        s += ps[(size_t)i * O + c];
        q += pq[(size_t)i * O + c];
    }
    __shared__ double ds[4][64], dq[4][64];
    ds[slot][threadIdx.x & 63] = s;
    dq[slot][threadIdx.x & 63] = q;
    __syncthreads();
    if (slot == 0) {
        int t = threadIdx.x & 63;
        double S = ds[0][t], Q = dq[0][t];
#pragma unroll
        for (int k = 1; k < 4; k++) { S += ds[k][t]; Q += dq[k][t]; }
        double m = S / cnt;
        double v = Q / cnt - m * m;
        float a  = g[c] * rsqrtf((float)v + EPSV);
        float sh = be[c] - (float)m * a;
        g_sc[stage][c] = a;
        g_sh[stage][c] = sh;
        if (coff >= 0) { g_csc[coff + c] = a; g_csh[coff + c] = sh; }
    }
}

// ---------------- w4 hi/lo bf16 split ----------------
__global__ void w4split_kernel(const float* __restrict__ w) {
    int i = blockIdx.x * 256 + threadIdx.x;            // 32768
    float v = w[i];
    __nv_bfloat16 h = __float2bfloat16(v);
    g_w4h[i] = h;
    g_w4l[i] = __float2bfloat16(v - __bfloat162float(h));
}

// =====================================================================
// s4_mma: stage-4 via mma.sync bf16 split GEMM (CTA 128m x 128n x K128)
//   D = Ah.Wh^T + Ah.Wl^T + Al.Wh^T  (fp32 acc, exact products)
//   A-load folds BN3+lrelu; epilogue: bias + fused stats + per-point max
//   smem: XOR-swizzled (16B chunk ^= row&7) for conflict-free ldmatrix
// =====================================================================
constexpr int S4_AH = 0;         // 32 KB: 128 rows x 16 chunks x 16B
constexpr int S4_AL = 32768;
constexpr int S4_BH = 65536;
constexpr int S4_BL = 98304;
constexpr int S4_SMEM = 131072;

__global__ __launch_bounds__(256, 1) void s4_mma_kernel(
    const float* __restrict__ A, const __nv_bfloat16* __restrict__ Wh,
    const __nv_bfloat16* __restrict__ Wl, const float* __restrict__ bias,
    const float* __restrict__ tsc, const float* __restrict__ tsh,
    float* __restrict__ ps, float* __restrict__ pq, float* __restrict__ cat) {
    extern __shared__ char smem[];
    uint32_t sb = smem_u32(smem);
    int tid = threadIdx.x;
    int lane = tid & 31, warp = tid >> 5;
    int wm = warp & 3, wn = warp >> 2;                 // warp tile 32m x 64n
    int m0 = blockIdx.y * 128;
    int n0 = blockIdx.x * 128;

    // ---- A: load fp32, BN+lrelu, hi/lo bf16, swizzled store ----
#pragma unroll
    for (int i = 0; i < 8; i++) {
        int idx = tid + 256 * i;                       // 2048 chunks
        int r = idx >> 4, c = idx & 15;
        const float* src = A + (size_t)(m0 + r) * 128 + c * 8;
        float4 v0 = *(const float4*)(src);
        float4 v1 = *(const float4*)(src + 4);
        float vv[8] = {v0.x, v0.y, v0.z, v0.w, v1.x, v1.y, v1.z, v1.w};
        uint32_t hp[4], lp[4];
#pragma unroll
        for (int e = 0; e < 4; e++) {
            uint32_t hw = 0, lw = 0;
#pragma unroll
            for (int t = 0; t < 2; t++) {
                int k = c * 8 + e * 2 + t;
                float v = vv[e * 2 + t] * tsc[k] + tsh[k];
                v = v >= 0.f ? v : SLOPE * v;
                __nv_bfloat16 h = __float2bfloat16(v);
                __nv_bfloat16 l = __float2bfloat16(v - __bfloat162float(h));
                hw |= (uint32_t)(*(uint16_t*)&h) << (16 * t);
                lw |= (uint32_t)(*(uint16_t*)&l) << (16 * t);
            }
            hp[e] = hw; lp[e] = lw;
        }
        int dst = (r * 16 + (c ^ (r & 7))) * 16;
        *(uint4*)(smem + S4_AH + dst) = make_uint4(hp[0], hp[1], hp[2], hp[3]);
        *(uint4*)(smem + S4_AL + dst) = make_uint4(lp[0], lp[1], lp[2], lp[3]);
    }
    // ---- B: copy pre-split bf16, swizzled ----
#pragma unroll
    for (int i = 0; i < 8; i++) {
        int idx = tid + 256 * i;
        int r = idx >> 4, c = idx & 15;
        uint4 hv = *(const uint4*)(Wh + (size_t)(n0 + r) * 128 + c * 8);
        uint4 lv = *(const uint4*)(Wl + (size_t)(n0 + r) * 128 + c * 8);
        int dst = (r * 16 + (c ^ (r & 7))) * 16;
        *(uint4*)(smem + S4_BH + dst) = hv;
        *(uint4*)(smem + S4_BL + dst) = lv;
    }
    __syncthreads();

    // per-lane ldmatrix row/ksel components
    int aRow0 = wm * 32 + (lane & 15);                 // +mt*16
    int aKsel = lane >> 4;                             // 0/1 (k-half)
    int bRow0 = wn * 64 + (lane & 7) + ((lane >> 4) << 3);  // +bt*16
    int bKsel = (lane >> 3) & 1;

    float acc[2][8][4];
#pragma unroll
    for (int a = 0; a < 2; a++)
#pragma unroll
        for (int b = 0; b < 8; b++)
#pragma unroll
            for (int d = 0; d < 4; d++) acc[a][b][d] = 0.f;

#pragma unroll 2
    for (int ks = 0; ks < 8; ks++) {
        uint32_t aH[2][4], aL[2][4], bH[16], bL[16];
#pragma unroll
        for (int mt = 0; mt < 2; mt++) {
            int row = aRow0 + mt * 16;
            int ch = (ks * 2 + aKsel) ^ (row & 7);
            uint32_t off = (uint32_t)(row * 16 + ch) * 16;
            ldsm4(aH[mt], sb + S4_AH + off);
            ldsm4(aL[mt], sb + S4_AL + off);
        }
#pragma unroll
        for (int bt = 0; bt < 4; bt++) {
            int row = bRow0 + bt * 16;
            int ch = (ks * 2 + bKsel) ^ (row & 7);
            uint32_t off = (uint32_t)(row * 16 + ch) * 16;
            ldsm4(&bH[bt * 4], sb + S4_BH + off);
            ldsm4(&bL[bt * 4], sb + S4_BL + off);
        }
#pragma unroll
        for (int mt = 0; mt < 2; mt++)
#pragma unroll
            for (int j = 0; j < 8; j++) {
                const uint32_t* bh = &bH[(j >> 1) * 4 + (j & 1) * 2];
                const uint32_t* bl = &bL[(j >> 1) * 4 + (j & 1) * 2];
                mma16816(acc[mt][j], aH[mt], bh);
                mma16816(acc[mt][j], aH[mt], bl);
                mma16816(acc[mt][j], aL[mt], bh);
            }
    }
    __syncthreads();

    // ---- C tile -> smem (reuse A/B region), add bias ----
    float* Cb = (float*)smem;                          // [128][132]
    int gr = lane >> 2, tg = lane & 3;
#pragma unroll
    for (int mt = 0; mt < 2; mt++) {
        int r0 = wm * 32 + mt * 16 + gr;
#pragma unroll
        for (int j = 0; j < 8; j++) {
            int col = wn * 64 + j * 8 + tg * 2;
            float b0 = bias[n0 + col], b1 = bias[n0 + col + 1];
            Cb[r0 * 132 + col]           = acc[mt][j][0] + b0;
            Cb[r0 * 132 + col + 1]       = acc[mt][j][1] + b1;
            Cb[(r0 + 8) * 132 + col]     = acc[mt][j][2] + b0;
            Cb[(r0 + 8) * 132 + col + 1] = acc[mt][j][3] + b1;
        }
    }
    __syncthreads();

    // ---- per-channel partial stats ----
    __shared__ float sps[2][128], spq[2][128];
    {
        int j = tid & 127, h = tid >> 7;
        float s = 0.f, q = 0.f;
        for (int r = h * 64; r < h * 64 + 64; r++) {
            float v = Cb[r * 132 + j];
            s += v; q += v * v;
        }
        sps[h][j] = s; spq[h][j] = q;
    }
    __syncthreads();
    if (tid < 128) {
        ps[(size_t)blockIdx.y * 256 + n0 + tid] = sps[0][tid] + sps[1][tid];
        pq[(size_t)blockIdx.y * 256 + n0 + tid] = spq[0][tid] + spq[1][tid];
    }
    // ---- per-point raw max -> cat (exact atomics) ----
    int p_first = m0 / KNN;
    int p_last  = (m0 + 127) / KNN;
    int npts = p_last - p_first + 1;
    for (int it = tid; it < npts * 128; it += 256) {
        int pl = it >> 7, j = it & 127;
        int p = p_first + pl;
        int r0 = max(p * KNN - m0, 0);
        int r1 = min(p * KNN + KNN - m0, 128);
        float mx = NEG_INF;
        for (int r = r0; r < r1; r++) mx = fmaxf(mx, Cb[r * 132 + j]);
        if (r1 > r0) amax_f(&cat[(size_t)p * 512 + 256 + n0 + j], mx);
    }
}

// =====================================================================
// gemm2 (unchanged from R10)
// =====================================================================
template <int BM, int BN, bool TRANS, bool WRITE_C, bool MAXF>
__global__ __launch_bounds__(256, 2) void gemm2_kernel(
    const float* __restrict__ A, const float* __restrict__ W,
    const float* __restrict__ bias, const float* __restrict__ tsc,
    const float* __restrict__ tsh, float* __restrict__ C,
    float* __restrict__ ps, float* __restrict__ pq, int K, int NN,
    float* __restrict__ cat, int coff) {
    constexpr int BK = 16;
    constexpr int WM = BM / 64;
    constexpr int WN = BN / 32;
    static_assert(WM * WN == 8, "8 warps");
    constexpr int ALD = BM * BK / (256 * 4);
    constexpr int WLD = BN * BK / (256 * 4);
    constexpr int PTS = BM / 20 + 2;

    __shared__ __align__(16) float As[2][BK][BM + 4];
    __shared__ __align__(16) float Ws[2][BK][BN + 4];
    __shared__ float rs[WM][BN];
    __shared__ float rq[WM][BN];
    __shared__ unsigned int smax[MAXF ? PTS : 1][MAXF ? BN : 1];

    int tid  = threadIdx.x;
    int warp = tid >> 5, lane = tid & 31;
    int wm = warp % WM, wn = warp / WM;
    int lm = lane & 7,  ln = lane >> 3;
    int m0 = blockIdx.y * BM;
    int n0 = blockIdx.x * BN;
    int p_base = m0 / KNN;

    if (MAXF) {
        for (int i = tid; i < PTS * BN; i += 256)
            ((unsigned int*)smax)[i] = 0u;
    }

    int mb = wm * 64 + lm * 4;
    int nb = wn * 32 + ln * 4;

    float4 apre[ALD], wpre[WLD];
    int r_a[ALD], kq_a[ALD];
#pragma unroll
    for (int u = 0; u < ALD; u++) { int i = tid + 256 * u; r_a[u] = i >> 2; kq_a[u] = i & 3; }
    int r_w[WLD], kq_w[WLD];
#pragma unroll
    for (int u = 0; u < WLD; u++) { int i = tid + 256 * u; r_w[u] = i >> 2; kq_w[u] = i & 3; }

    int tiles = K / BK;
    unsigned long long accp[8][4];
#pragma unroll
    for (int i = 0; i < 8; i++)
#pragma unroll
        for (int jp = 0; jp < 4; jp++) accp[i][jp] = 0ull;

#pragma unroll
    for (int u = 0; u < ALD; u++)
        apre[u] = *(const float4*)(A + (size_t)(m0 + r_a[u]) * K + kq_a[u] * 4);
#pragma unroll
    for (int u = 0; u < WLD; u++)
        wpre[u] = *(const float4*)(W + (size_t)(n0 + r_w[u]) * K + kq_w[u] * 4);
    {
#pragma unroll
        for (int u = 0; u < ALD; u++) {
            float vals[4] = {apre[u].x, apre[u].y, apre[u].z, apre[u].w};
#pragma unroll
            for (int e = 0; e < 4; e++) {
                float v = vals[e];
                if (TRANS) {
                    int kk = kq_a[u] * 4 + e;
                    v = v * tsc[kk] + tsh[kk];
                    v = v >= 0.f ? v : SLOPE * v;
                }
                As[0][kq_a[u] * 4 + e][r_a[u]] = v;
            }
        }
#pragma unroll
        for (int u = 0; u < WLD; u++) {
            Ws[0][kq_w[u] * 4 + 0][r_w[u]] = wpre[u].x;
            Ws[0][kq_w[u] * 4 + 1][r_w[u]] = wpre[u].y;
            Ws[0][kq_w[u] * 4 + 2][r_w[u]] = wpre[u].z;
            Ws[0][kq_w[u] * 4 + 3][r_w[u]] = wpre[u].w;
        }
    }
    __syncthreads();

    for (int t = 0; t < tiles; t++) {
        int cur = t & 1, nxt = cur ^ 1;
        bool has_next = (t + 1) < tiles;
        if (has_next) {
            int k0 = (t + 1) * BK;
#pragma unroll
            for (int u = 0; u < ALD; u++)
                apre[u] = *(const float4*)(A + (size_t)(m0 + r_a[u]) * K + k0 + kq_a[u] * 4);
#pragma unroll
            for (int u = 0; u < WLD; u++)
                wpre[u] = *(const float4*)(W + (size_t)(n0 + r_w[u]) * K + k0 + kq_w[u] * 4);
        }
#pragma unroll
        for (int k = 0; k < BK; k++) {
            float4 a0 = *(const float4*)&As[cur][k][mb];
            float4 a1 = *(const float4*)&As[cur][k][mb + 32];
            ulonglong2 b0 = *(const ulonglong2*)&Ws[cur][k][nb];
            ulonglong2 b1 = *(const ulonglong2*)&Ws[cur][k][nb + 16];
            unsigned long long bp[4] = {b0.x, b0.y, b1.x, b1.y};
            float av[8] = {a0.x, a0.y, a0.z, a0.w, a1.x, a1.y, a1.z, a1.w};
#pragma unroll
            for (int i = 0; i < 8; i++) {
                unsigned long long ap = pack2b(av[i]);
#pragma unroll
                for (int jp = 0; jp < 4; jp++) ffma2(accp[i][jp], ap, bp[jp]);
            }
        }
        if (has_next) {
            int k0 = (t + 1) * BK;
#pragma unroll
            for (int u = 0; u < ALD; u++) {
                float vals[4] = {apre[u].x, apre[u].y, apre[u].z, apre[u].w};
#pragma unroll
                for (int e = 0; e < 4; e++) {
                    float v = vals[e];
                    if (TRANS) {
                        int kk = k0 + kq_a[u] * 4 + e;
                        v = v * tsc[kk] + tsh[kk];
                        v = v >= 0.f ? v : SLOPE * v;
                    }
                    As[nxt][kq_a[u] * 4 + e][r_a[u]] = v;
                }
            }
#pragma unroll
            for (int u = 0; u < WLD; u++) {
                Ws[nxt][kq_w[u] * 4 + 0][r_w[u]] = wpre[u].x;
                Ws[nxt][kq_w[u] * 4 + 1][r_w[u]] = wpre[u].y;
                Ws[nxt][kq_w[u] * 4 + 2][r_w[u]] = wpre[u].z;
                Ws[nxt][kq_w[u] * 4 + 3][r_w[u]] = wpre[u].w;
            }
        }
        __syncthreads();
    }

    float bia[8];
#pragma unroll
    for (int j = 0; j < 8; j++) {
        int n = n0 + nb + (j < 4 ? j : 12 + j);
        bia[j] = bias[n];
    }
    float s_j[8] = {}, q_j[8] = {};
    float runmax[8];
    int cur_pl = -1;
#pragma unroll
    for (int i = 0; i < 8; i++) {
        int mrow = mb + (i < 4 ? i : 28 + i);
        int m = m0 + mrow;
        float vrow[8];
        unpack2(accp[i][0], vrow[0], vrow[1]);
        unpack2(accp[i][1], vrow[2], vrow[3]);
        unpack2(accp[i][2], vrow[4], vrow[5]);
        unpack2(accp[i][3], vrow[6], vrow[7]);
#pragma unroll
        for (int j = 0; j < 8; j++) {
            float v = vrow[j] + bia[j];
            vrow[j] = v;
            s_j[j] += v;
            q_j[j] += v * v;
        }
        if (WRITE_C) {
            *(float4*)(C + (size_t)m * NN + n0 + nb) =
                make_float4(vrow[0], vrow[1], vrow[2], vrow[3]);
            *(float4*)(C + (size_t)m * NN + n0 + nb + 16) =
                make_float4(vrow[4], vrow[5], vrow[6], vrow[7]);
        }
        if (MAXF) {
            int pl = m / KNN - p_base;
            if (pl != cur_pl) {
                if (cur_pl >= 0) {
#pragma unroll
                    for (int j = 0; j < 8; j++) {
                        int c = nb + (j < 4 ? j : 12 + j);
                        atomicMax(&smax[cur_pl][c], fenc(runmax[j]));
                    }
                }
                cur_pl = pl;
#pragma unroll
                for (int j = 0; j < 8; j++) runmax[j] = vrow[j];
            } else {
#pragma unroll
                for (int j = 0; j < 8; j++) runmax[j] = fmaxf(runmax[j], vrow[j]);
            }
        }
    }
    if (MAXF && cur_pl >= 0) {
#pragma unroll
        for (int j = 0; j < 8; j++) {
            int c = nb + (j < 4 ? j : 12 + j);
            atomicMax(&smax[cur_pl][c], fenc(runmax[j]));
        }
    }
#pragma unroll
    for (int off = 1; off < 8; off <<= 1) {
#pragma unroll
        for (int j = 0; j < 8; j++) {
            s_j[j] += __shfl_xor_sync(0xffffffffu, s_j[j], off);
            q_j[j] += __shfl_xor_sync(0xffffffffu, q_j[j], off);
        }
    }
    __syncthreads();
    if (lm == 0) {
#pragma unroll
        for (int j = 0; j < 8; j++) {
            int c = nb + (j < 4 ? j : 12 + j);
            rs[wm][c] = s_j[j];
            rq[wm][c] = q_j[j];
        }
    }
    __syncthreads();
    for (int c = tid; c < BN; c += 256) {
        float s = 0.f, q = 0.f;
#pragma unroll
        for (int w = 0; w < WM; w++) { s += rs[w][c]; q += rq[w][c]; }
        ps[(size_t)blockIdx.y * NN + n0 + c] = s;
        pq[(size_t)blockIdx.y * NN + n0 + c] = q;
    }
    if (MAXF) {
        int npts = (m0 + BM - 1) / KNN - p_base + 1;
        for (int idx = tid; idx < npts * BN; idx += 256) {
            int pl = idx / BN, c = idx % BN;
            float v = fdec(smax[pl][c]);
            if (v > NEG_INF)
                amax_f(&cat[(size_t)(p_base + pl) * 512 + coff + n0 + c], v);
        }
    }
}

// ---------------- final ----------------
__global__ void final_kernel(float* __restrict__ out) {
    int i = blockIdx.x * 256 + threadIdx.x;
    int c = i & 1023;
    float v = g_sc[5][c] * g_t6[i] + g_sh[5][c];
    out[i] = v >= 0.f ? v : SLOPE * v;
}

// ---------------- launch ----------------
extern "C" void kernel_launch(void* const* d_in, const int* in_sizes, int n_in,
                              void* d_out, int out_size) {
    const float* x  = (const float*)d_in[0];
    const float* w1 = (const float*)d_in[1];
    const float* b1 = (const float*)d_in[2];
    const float* g1 = (const float*)d_in[3];
    const float* be1= (const float*)d_in[4];
    const float* w2 = (const float*)d_in[5];
    const float* b2 = (const float*)d_in[6];
    const float* g2 = (const float*)d_in[7];
    const float* be2= (const float*)d_in[8];
    const float* w3 = (const float*)d_in[9];
    const float* b3 = (const float*)d_in[10];
    const float* g3 = (const float*)d_in[11];
    const float* be3= (const float*)d_in[12];
    const float* w4 = (const float*)d_in[13];
    const float* b4 = (const float*)d_in[14];
    const float* g4 = (const float*)d_in[15];
    const float* be4= (const float*)d_in[16];
    const float* w5 = (const float*)d_in[17];
    const float* b5 = (const float*)d_in[18];
    const float* g5 = (const float*)d_in[19];
    const float* be5= (const float*)d_in[20];
    const float* w6 = (const float*)d_in[21];
    const float* b6 = (const float*)d_in[22];
    const float* g6 = (const float*)d_in[23];
    const float* be6= (const float*)d_in[24];
    float* out = (float*)d_out;

    float *t1, *t2, *t3, *t5, *t6, *cat, *scb, *shb, *csc, *csh, *ps, *pq;
    __nv_bfloat16 *w4h, *w4l;
    cudaGetSymbolAddress((void**)&t1, g_t1);
    cudaGetSymbolAddress((void**)&t2, g_t2);
    cudaGetSymbolAddress((void**)&t3, g_t3);
    cudaGetSymbolAddress((void**)&t5, g_t5);
    cudaGetSymbolAddress((void**)&t6, g_t6);
    cudaGetSymbolAddress((void**)&cat, g_cat);
    cudaGetSymbolAddress((void**)&scb, g_sc);
    cudaGetSymbolAddress((void**)&shb, g_sh);
    cudaGetSymbolAddress((void**)&csc, g_csc);
    cudaGetSymbolAddress((void**)&csh, g_csh);
    cudaGetSymbolAddress((void**)&ps, g_ps);
    cudaGetSymbolAddress((void**)&pq, g_pq);
    cudaGetSymbolAddress((void**)&w4h, g_w4h);
    cudaGetSymbolAddress((void**)&w4l, g_w4l);

    cudaFuncSetAttribute(s4_mma_kernel, cudaFuncAttributeMaxDynamicSharedMemorySize, S4_SMEM);

    // init cat to -inf
    init_cat<<<P * 512 / 256, 256>>>(cat);

    // KNN
    xx_kernel<<<P / 256, 256>>>(x);
    pd_kernel<<<dim3(16, 16, Bb), 256>>>(x);
    topk_kernel<<<P / 16, 512>>>();

    // W4 split (independent)
    w4split_kernel<<<128, 256>>>(w4);

    // Stage 1
    qp_kernel<<<dim3(16, Bb), 256>>>(x, w1);
    s1_kernel<<<P, 256>>>(b1, ps, pq, cat);
    stats_finalize<<<1, 256>>>(ps, pq, P, 64, (float)M4, 0, 0, g1, be1);

    // Stage 2
    gemm2_kernel<256, 64, true, true, true><<<dim3(1, M4 / 256), 256>>>(
        t1, w2, b2, scb + 0 * 1024, shb + 0 * 1024, t2, ps, pq, 64, 64, cat, 64);
    stats_finalize<<<1, 256>>>(ps, pq, M4 / 256, 64, (float)M4, 1, 64, g2, be2);

    // Stage 3
    gemm2_kernel<128, 128, true, true, true><<<dim3(1, M4 / 128), 256>>>(
        t2, w3, b3, scb + 1 * 1024, shb + 1 * 1024, t3, ps, pq, 64, 128, cat, 128);
    stats_finalize<<<2, 256>>>(ps, pq, M4 / 128, 128, (float)M4, 2, 128, g3, be3);

    // Stage 4: mma.sync bf16-split GEMM, fused stats + x4 max (no t4 write)
    s4_mma_kernel<<<dim3(2, M4 / 128), 256, S4_SMEM>>>(
        t3, w4h, w4l, b4, scb + 2 * 1024, shb + 2 * 1024, ps, pq, cat);
    stats_finalize<<<4, 256>>>(ps, pq, M4 / 128, 256, (float)M4, 3, 256, g4, be4);

    // Stage 5
    gemm2_kernel<128, 128, true, true, false><<<dim3(2, P / 128), 256>>>(
        cat, w5, b5, csc, csh, t5, ps, pq, 512, 256, nullptr, 0);
    stats_finalize<<<4, 256>>>(ps, pq, P / 128, 256, (float)P, 4, -1, g5, be5);

    // Stage 6
    gemm2_kernel<128, 128, true, true, false><<<dim3(8, P / 128), 256>>>(
        t5, w6, b6, scb + 4 * 1024, shb + 4 * 1024, t6, ps, pq, 256, 1024, nullptr, 0);
    stats_finalize<<<16, 256>>>(ps, pq, P / 128, 1024, (float)P, 5, -1, g6, be6);

    // Final
    final_kernel<<<P * 1024 / 256, 256>>>(out);
}

// round 13
// speedup vs baseline: 1.2863x; 1.0642x over previous
#include <cuda_runtime.h>
#include <cuda_bf16.h>
#include <cstdint>
#include <math.h>

// ---------------- Problem constants ----------------
constexpr int Bb   = 8;
constexpr int Dd   = 60;
constexpr int NP   = 1024;
constexpr int KNN  = 20;
constexpr int P    = Bb * NP;        // 8192 points
constexpr int M4   = P * KNN;        // 163840 graph-feature rows
constexpr float EPSV  = 1e-5f;
constexpr float SLOPE = 0.2f;

#define NEG_INF (__int_as_float(0xff800000))

// ---------------- packed f32x2 helpers (gemm2) ----------------
__device__ __forceinline__ unsigned long long pack2b(float v) {
    unsigned long long r;
    asm("mov.b64 %0, {%1, %1};" : "=l"(r) : "f"(v));
    return r;
}
__device__ __forceinline__ void ffma2(unsigned long long& d, unsigned long long a,
                                      unsigned long long b) {
    asm("fma.rn.f32x2 %0, %1, %2, %0;" : "+l"(d) : "l"(a), "l"(b));
}
__device__ __forceinline__ void unpack2(unsigned long long p, float& lo, float& hi) {
    asm("mov.b64 {%0, %1}, %2;" : "=f"(lo), "=f"(hi) : "l"(p));
}
// exact float max via atomics (order-independent => deterministic)
__device__ __forceinline__ void amax_f(float* a, float v) {
    if (v >= 0.f) atomicMax((int*)a, __float_as_int(v));
    else          atomicMin((unsigned int*)a, __float_as_uint(v));
}
// order-preserving float->uint key
__device__ __forceinline__ unsigned int fenc(float f) {
    unsigned int b = __float_as_uint(f);
    return b ^ ((unsigned int)((int)b >> 31) | 0x80000000u);
}
__device__ __forceinline__ float fdec(unsigned int u) {
    unsigned int b = (u & 0x80000000u) ? (u ^ 0x80000000u) : ~u;
    return __uint_as_float(b);
}

// ---------------- mma.sync helpers ----------------
__device__ __forceinline__ uint32_t smem_u32(const void* p) {
    uint32_t a;
    asm("{ .reg .u64 t; cvta.to.shared.u64 t, %1; cvt.u32.u64 %0, t; }" : "=r"(a) : "l"(p));
    return a;
}
__device__ __forceinline__ void ldsm4(uint32_t* r, uint32_t addr) {
    asm volatile("ldmatrix.sync.aligned.m8n8.x4.shared.b16 {%0,%1,%2,%3}, [%4];"
        : "=r"(r[0]), "=r"(r[1]), "=r"(r[2]), "=r"(r[3]) : "r"(addr));
}
__device__ __forceinline__ void mma16816(float* d, const uint32_t* a, const uint32_t* b) {
    asm volatile("mma.sync.aligned.m16n8k16.row.col.f32.bf16.bf16.f32 "
        "{%0,%1,%2,%3}, {%4,%5,%6,%7}, {%8,%9}, {%0,%1,%2,%3};"
        : "+f"(d[0]), "+f"(d[1]), "+f"(d[2]), "+f"(d[3])
        : "r"(a[0]), "r"(a[1]), "r"(a[2]), "r"(a[3]), "r"(b[0]), "r"(b[1]));
}

// ---------------- Device scratch ----------------
__device__ float g_xx[P];
__device__ float g_pd[(size_t)Bb * NP * NP];
__device__ int   g_idx[M4];
__device__ float g_q[(size_t)P * 64];
__device__ float g_p[(size_t)P * 64];
__device__ float g_t1[(size_t)M4 * 64];
__device__ float g_t2[(size_t)M4 * 64];
__device__ float g_t3[(size_t)M4 * 128];
__device__ float g_cat[(size_t)P * 512];
__device__ float g_t5[(size_t)P * 256];
__device__ float g_t6[(size_t)P * 1024];
__device__ float g_ps[1 << 20];
__device__ float g_pq[1 << 20];
__device__ float g_sc[6][1024];
__device__ float g_sh[6][1024];
__device__ float g_csc[512];
__device__ float g_csh[512];
__device__ __nv_bfloat16 g_w3h[128 * 64],   g_w3l[128 * 64];
__device__ __nv_bfloat16 g_w4h[256 * 128],  g_w4l[256 * 128];
__device__ __nv_bfloat16 g_w5h[256 * 512],  g_w5l[256 * 512];
__device__ __nv_bfloat16 g_w6h[1024 * 256], g_w6l[1024 * 256];

// ---------------- init cat to -inf ----------------
__global__ void init_cat(float* __restrict__ cat) {
    cat[blockIdx.x * 256 + threadIdx.x] = NEG_INF;
}

// ---------------- xx ----------------
__global__ void xx_kernel(const float* __restrict__ x) {
    int i = blockIdx.x * 256 + threadIdx.x;
    int b = i >> 10, n = i & 1023;
    const float* xb = x + (size_t)b * Dd * NP + n;
    float s = 0.f;
#pragma unroll
    for (int d = 0; d < Dd; d++) { float v = xb[d * NP]; s += v * v; }
    g_xx[i] = s;
}

// ---------------- pd ----------------
__global__ void pd_kernel(const float* __restrict__ x) {
    int b  = blockIdx.z;
    int n0 = blockIdx.y * 64;
    int m0 = blockIdx.x * 64;
    __shared__ float Xa[Dd][64];
    __shared__ float Xb[Dd][64];
    const float* xb = x + (size_t)b * Dd * NP;
    for (int l = threadIdx.x; l < Dd * 64; l += 256) {
        int d = l >> 6, mm = l & 63;
        Xa[d][mm] = xb[d * NP + n0 + mm];
        Xb[d][mm] = xb[d * NP + m0 + mm];
    }
    __syncthreads();
    int tx = threadIdx.x & 15, ty = threadIdx.x >> 4;
    float acc[4][4] = {};
#pragma unroll
    for (int d = 0; d < Dd; d++) {
        float a[4], c[4];
#pragma unroll
        for (int i = 0; i < 4; i++) a[i] = Xa[d][ty * 4 + i];
#pragma unroll
        for (int j = 0; j < 4; j++) c[j] = Xb[d][tx * 4 + j];
#pragma unroll
        for (int i = 0; i < 4; i++)
#pragma unroll
            for (int j = 0; j < 4; j++) acc[i][j] += a[i] * c[j];
    }
#pragma unroll
    for (int i = 0; i < 4; i++) {
        int n = n0 + ty * 4 + i;
        float xn = g_xx[b * NP + n];
#pragma unroll
        for (int j = 0; j < 4; j++) {
            int m = m0 + tx * 4 + j;
            g_pd[((size_t)b << 20) + (size_t)n * NP + m] =
                2.f * acc[i][j] - xn - g_xx[b * NP + m];
        }
    }
}

// ---------------- warp-per-row top-k ----------------
__global__ __launch_bounds__(512) void topk_kernel() {
    int warp = threadIdx.x >> 5, lane = threadIdx.x & 31;
    int bn = blockIdx.x * 16 + warp;
    const float* row = g_pd + (size_t)bn * NP;
    float v[32];
#pragma unroll
    for (int j = 0; j < 32; j++) v[j] = row[j * 32 + lane];
    float bv = v[0]; int bs = 0;
#pragma unroll
    for (int j = 1; j < 32; j++)
        if (v[j] > bv) { bv = v[j]; bs = j; }
    int* out = g_idx + bn * KNN;
    for (int it = 0; it < KNN; it++) {
        float rv = bv;
        int   ri = bs * 32 + lane;
#pragma unroll
        for (int off = 16; off > 0; off >>= 1) {
            float ov = __shfl_xor_sync(0xffffffffu, rv, off);
            int   oi = __shfl_xor_sync(0xffffffffu, ri, off);
            if (ov > rv || (ov == rv && oi < ri)) { rv = ov; ri = oi; }
        }
        if (lane == 0) out[it] = ri;
        if ((ri & 31) == lane) {
            v[ri >> 5] = NEG_INF;
            bv = v[0]; bs = 0;
#pragma unroll
            for (int j = 1; j < 32; j++)
                if (v[j] > bv) { bv = v[j]; bs = j; }
        }
    }
}

// ---------------- qp ----------------
__global__ void qp_kernel(const float* __restrict__ x, const float* __restrict__ w1) {
    int b  = blockIdx.y;
    int m0 = blockIdx.x * 64;
    __shared__ float xs[Dd][64];
    __shared__ float ws[64][120];
    const float* xb = x + (size_t)b * Dd * NP;
    for (int l = threadIdx.x; l < Dd * 64; l += 256) {
        int d = l >> 6, m = l & 63;
        xs[d][m] = xb[d * NP + m0 + m];
    }
    for (int l = threadIdx.x; l < 64 * 120; l += 256) ws[l / 120][l % 120] = w1[l];
    __syncthreads();
    int tx = threadIdx.x & 15, ty = threadIdx.x >> 4;
    float qa[4][4] = {}, pa[4][4] = {};
#pragma unroll
    for (int d = 0; d < Dd; d++) {
        float wa[4], wb[4], xm[4];
#pragma unroll
        for (int i = 0; i < 4; i++) {
            wa[i] = ws[ty * 4 + i][d];
            wb[i] = ws[ty * 4 + i][60 + d] - wa[i];
        }
#pragma unroll
        for (int j = 0; j < 4; j++) xm[j] = xs[d][tx * 4 + j];
#pragma unroll
        for (int i = 0; i < 4; i++)
#pragma unroll
            for (int j = 0; j < 4; j++) {
                qa[i][j] += wa[i] * xm[j];
                pa[i][j] += wb[i] * xm[j];
            }
    }
#pragma unroll
    for (int i = 0; i < 4; i++)
#pragma unroll
        for (int j = 0; j < 4; j++) {
            int o = ty * 4 + i, m = m0 + tx * 4 + j;
            size_t base = ((size_t)b * NP + m) * 64 + o;
            g_q[base] = qa[i][j];
            g_p[base] = pa[i][j];
        }
}

// ---------------- s1 ----------------
__global__ __launch_bounds__(256) void s1_kernel(const float* __restrict__ b1,
                                                 float* __restrict__ ps,
                                                 float* __restrict__ pq,
                                                 float* __restrict__ cat) {
    int bn = blockIdx.x;
    int tid = threadIdx.x;
    int c = tid & 63, js = tid >> 6;
    int b = bn >> 10;
    float pv = g_p[(size_t)bn * 64 + c] + b1[c];
    int rbase = bn * KNN;
    float mx = NEG_INF, s = 0.f, q = 0.f;
#pragma unroll
    for (int jj = 0; jj < 5; jj++) {
        int row = rbase + js + jj * 4;
        int m = g_idx[row];
        float v = g_q[((size_t)(b << 10) + m) * 64 + c] + pv;
        g_t1[(size_t)row * 64 + c] = v;
        mx = fmaxf(mx, v); s += v; q += v * v;
    }
    __shared__ float smx[4][64], ssm[4][64], sqm[4][64];
    smx[js][c] = mx; ssm[js][c] = s; sqm[js][c] = q;
    __syncthreads();
    if (js == 0) {
        float M = smx[0][c], S = ssm[0][c], Q = sqm[0][c];
#pragma unroll
        for (int k = 1; k < 4; k++) {
            M = fmaxf(M, smx[k][c]); S += ssm[k][c]; Q += sqm[k][c];
        }
        cat[(size_t)bn * 512 + c] = M;
        ps[(size_t)bn * 64 + c] = S;
        pq[(size_t)bn * 64 + c] = Q;
    }
}

// ---------------- stats finalize ----------------
__global__ void stats_finalize(const float* __restrict__ ps, const float* __restrict__ pq,
                               int nb, int O, float cnt, int stage, int coff,
                               const float* __restrict__ g, const float* __restrict__ be) {
    int c = blockIdx.x * 64 + (threadIdx.x & 63);
    int slot = threadIdx.x >> 6;
    double s = 0.0, q = 0.0;
    for (int i = slot; i < nb; i += 4) {
        s += ps[(size_t)i * O + c];
        q += pq[(size_t)i * O + c];
    }
    __shared__ double ds[4][64], dq[4][64];
    ds[slot][threadIdx.x & 63] = s;
    dq[slot][threadIdx.x & 63] = q;
    __syncthreads();
    if (slot == 0) {
        int t = threadIdx.x & 63;
        double S = ds[0][t], Q = dq[0][t];
#pragma unroll
        for (int k = 1; k < 4; k++) { S += ds[k][t]; Q += dq[k][t]; }
        double m = S / cnt;
        double v = Q / cnt - m * m;
        float a  = g[c] * rsqrtf((float)v + EPSV);
        float sh = be[c] - (float)m * a;
        g_sc[stage][c] = a;
        g_sh[stage][c] = sh;
        if (coff >= 0) { g_csc[coff + c] = a; g_csh[coff + c] = sh; }
    }
}

// ---------------- generic weight hi/lo bf16 split ----------------
__global__ void wsplit_kernel(const float* __restrict__ w,
                              __nv_bfloat16* __restrict__ dh,
                              __nv_bfloat16* __restrict__ dl) {
    int i = blockIdx.x * 256 + threadIdx.x;
    float v = w[i];
    __nv_bfloat16 h = __float2bfloat16(v);
    dh[i] = h;
    dl[i] = __float2bfloat16(v - __bfloat162float(h));
}

// =====================================================================
// mma_gemm: generalized bf16-split HMMA GEMM (CTA 128m x 128n, K-chunked)
//   D = Ah.Wh^T + Ah.Wl^T + Al.Wh^T  (fp32 acc, exact products)
//   KC = K-chunk (64 or 128); accumulators persist across chunks.
//   A-load folds per-k scale/shift + lrelu; epilogue: bias + stats
//   (+ optional global C write, optional per-point max into cat)
// =====================================================================
template <int KC, bool WRITE_C, bool MAXF>
__global__ __launch_bounds__(256, 1) void mma_gemm_kernel(
    const float* __restrict__ A, const __nv_bfloat16* __restrict__ Wh,
    const __nv_bfloat16* __restrict__ Wl, const float* __restrict__ bias,
    const float* __restrict__ tsc, const float* __restrict__ tsh,
    float* __restrict__ C, float* __restrict__ ps, float* __restrict__ pq,
    int K, int NN, float* __restrict__ cat, int coff) {
    constexpr int CH = KC / 8;                 // 16B chunks per row
    constexpr int TILE = 128 * CH * 16;        // bytes per bf16 tile
    extern __shared__ char smem[];
    uint32_t sb = smem_u32(smem);
    const int AH = 0, AL = TILE, BH = 2 * TILE, BL = 3 * TILE;

    int tid = threadIdx.x;
    int lane = tid & 31, warp = tid >> 5;
    int wm = warp & 3, wn = warp >> 2;         // warp tile 32m x 64n
    int m0 = blockIdx.y * 128;
    int n0 = blockIdx.x * 128;

    int aRow0 = wm * 32 + (lane & 15);
    int aKsel = lane >> 4;
    int bRow0 = wn * 64 + (lane & 7) + ((lane >> 4) << 3);
    int bKsel = (lane >> 3) & 1;

    float acc[2][8][4];
#pragma unroll
    for (int a = 0; a < 2; a++)
#pragma unroll
        for (int b = 0; b < 8; b++)
#pragma unroll
            for (int d = 0; d < 4; d++) acc[a][b][d] = 0.f;

    for (int k0 = 0; k0 < K; k0 += KC) {
        if (k0 > 0) __syncthreads();
        // ---- A chunk: fp32 load, scale+lrelu, hi/lo split, swizzled ----
#pragma unroll
        for (int i = 0; i < CH / 2; i++) {
            int idx = tid + 256 * i;
            int r = idx / CH, c = idx % CH;
            const float* src = A + (size_t)(m0 + r) * K + k0 + c * 8;
            float4 v0 = *(const float4*)(src);
            float4 v1 = *(const float4*)(src + 4);
            float vv[8] = {v0.x, v0.y, v0.z, v0.w, v1.x, v1.y, v1.z, v1.w};
            uint32_t hp[4], lp[4];
#pragma unroll
            for (int e = 0; e < 4; e++) {
                uint32_t hw = 0, lw = 0;
#pragma unroll
                for (int t = 0; t < 2; t++) {
                    int k = k0 + c * 8 + e * 2 + t;
                    float v = vv[e * 2 + t] * tsc[k] + tsh[k];
                    v = v >= 0.f ? v : SLOPE * v;
                    __nv_bfloat16 h = __float2bfloat16(v);
                    __nv_bfloat16 l = __float2bfloat16(v - __bfloat162float(h));
                    hw |= (uint32_t)(*(uint16_t*)&h) << (16 * t);
                    lw |= (uint32_t)(*(uint16_t*)&l) << (16 * t);
                }
                hp[e] = hw; lp[e] = lw;
            }
            int dst = (r * CH + (c ^ (r & 7))) * 16;
            *(uint4*)(smem + AH + dst) = make_uint4(hp[0], hp[1], hp[2], hp[3]);
            *(uint4*)(smem + AL + dst) = make_uint4(lp[0], lp[1], lp[2], lp[3]);
        }
        // ---- B chunk: copy pre-split bf16, swizzled ----
#pragma unroll
        for (int i = 0; i < CH / 2; i++) {
            int idx = tid + 256 * i;
            int r = idx / CH, c = idx % CH;
            uint4 hv = *(const uint4*)(Wh + (size_t)(n0 + r) * K + k0 + c * 8);
            uint4 lv = *(const uint4*)(Wl + (size_t)(n0 + r) * K + k0 + c * 8);
            int dst = (r * CH + (c ^ (r & 7))) * 16;
            *(uint4*)(smem + BH + dst) = hv;
            *(uint4*)(smem + BL + dst) = lv;
        }
        __syncthreads();

#pragma unroll
        for (int ks = 0; ks < KC / 16; ks++) {
            uint32_t aHr[2][4], aLr[2][4], bHr[16], bLr[16];
#pragma unroll
            for (int mt = 0; mt < 2; mt++) {
                int row = aRow0 + mt * 16;
                int ch = (ks * 2 + aKsel) ^ (row & 7);
                uint32_t off = (uint32_t)(row * CH + ch) * 16;
                ldsm4(aHr[mt], sb + AH + off);
                ldsm4(aLr[mt], sb + AL + off);
            }
#pragma unroll
            for (int bt = 0; bt < 4; bt++) {
                int row = bRow0 + bt * 16;
                int ch = (ks * 2 + bKsel) ^ (row & 7);
                uint32_t off = (uint32_t)(row * CH + ch) * 16;
                ldsm4(&bHr[bt * 4], sb + BH + off);
                ldsm4(&bLr[bt * 4], sb + BL + off);
            }
#pragma unroll
            for (int mt = 0; mt < 2; mt++)
#pragma unroll
                for (int j = 0; j < 8; j++) {
                    const uint32_t* bh = &bHr[(j >> 1) * 4 + (j & 1) * 2];
                    const uint32_t* bl = &bLr[(j >> 1) * 4 + (j & 1) * 2];
                    mma16816(acc[mt][j], aHr[mt], bh);
                    mma16816(acc[mt][j], aHr[mt], bl);
                    mma16816(acc[mt][j], aLr[mt], bh);
                }
        }
    }
    __syncthreads();

    // ---- C tile -> smem (reuse tiles), add bias ----
    float* Cb = (float*)smem;                  // [128][132]
    int gr = lane >> 2, tg = lane & 3;
#pragma unroll
    for (int mt = 0; mt < 2; mt++) {
        int r0 = wm * 32 + mt * 16 + gr;
#pragma unroll
        for (int j = 0; j < 8; j++) {
            int col = wn * 64 + j * 8 + tg * 2;
            float b0 = bias[n0 + col], b1 = bias[n0 + col + 1];
            Cb[r0 * 132 + col]           = acc[mt][j][0] + b0;
            Cb[r0 * 132 + col + 1]       = acc[mt][j][1] + b1;
            Cb[(r0 + 8) * 132 + col]     = acc[mt][j][2] + b0;
            Cb[(r0 + 8) * 132 + col + 1] = acc[mt][j][3] + b1;
        }
    }
    __syncthreads();

    if (WRITE_C) {
        for (int idx = tid; idx < 128 * 32; idx += 256) {
            int r = idx >> 5, c4 = idx & 31;
            float4 v = *(float4*)&Cb[r * 132 + c4 * 4];
            *(float4*)(C + (size_t)(m0 + r) * NN + n0 + c4 * 4) = v;
        }
    }
    // ---- per-channel partial stats ----
    __shared__ float sps[2][128], spq[2][128];
    {
        int j = tid & 127, h = tid >> 7;
        float s = 0.f, q = 0.f;
        for (int r = h * 64; r < h * 64 + 64; r++) {
            float v = Cb[r * 132 + j];
            s += v; q += v * v;
        }
        sps[h][j] = s; spq[h][j] = q;
    }
    __syncthreads();
    if (tid < 128) {
        ps[(size_t)blockIdx.y * NN + n0 + tid] = sps[0][tid] + sps[1][tid];
        pq[(size_t)blockIdx.y * NN + n0 + tid] = spq[0][tid] + spq[1][tid];
    }
    // ---- per-point raw max -> cat ----
    if (MAXF) {
        int p_first = m0 / KNN;
        int p_last  = (m0 + 127) / KNN;
        int npts = p_last - p_first + 1;
        for (int it = tid; it < npts * 128; it += 256) {
            int pl = it >> 7, j = it & 127;
            int p = p_first + pl;
            int r0 = max(p * KNN - m0, 0);
            int r1 = min(p * KNN + KNN - m0, 128);
            float mx = NEG_INF;
            for (int r = r0; r < r1; r++) mx = fmaxf(mx, Cb[r * 132 + j]);
            if (r1 > r0) amax_f(&cat[(size_t)p * 512 + coff + n0 + j], mx);
        }
    }
}

// =====================================================================
// gemm2 (stage 2 only; unchanged)
// =====================================================================
template <int BM, int BN, bool TRANS, bool WRITE_C, bool MAXF>
__global__ __launch_bounds__(256, 2) void gemm2_kernel(
    const float* __restrict__ A, const float* __restrict__ W,
    const float* __restrict__ bias, const float* __restrict__ tsc,
    const float* __restrict__ tsh, float* __restrict__ C,
    float* __restrict__ ps, float* __restrict__ pq, int K, int NN,
    float* __restrict__ cat, int coff) {
    constexpr int BK = 16;
    constexpr int WM = BM / 64;
    constexpr int WN = BN / 32;
    static_assert(WM * WN == 8, "8 warps");
    constexpr int ALD = BM * BK / (256 * 4);
    constexpr int WLD = BN * BK / (256 * 4);
    constexpr int PTS = BM / 20 + 2;

    __shared__ __align__(16) float As[2][BK][BM + 4];
    __shared__ __align__(16) float Ws[2][BK][BN + 4];
    __shared__ float rs[WM][BN];
    __shared__ float rq[WM][BN];
    __shared__ unsigned int smax[MAXF ? PTS : 1][MAXF ? BN : 1];

    int tid  = threadIdx.x;
    int warp = tid >> 5, lane = tid & 31;
    int wm = warp % WM, wn = warp / WM;
    int lm = lane & 7,  ln = lane >> 3;
    int m0 = blockIdx.y * BM;
    int n0 = blockIdx.x * BN;
    int p_base = m0 / KNN;

    if (MAXF) {
        for (int i = tid; i < PTS * BN; i += 256)
            ((unsigned int*)smax)[i] = 0u;
    }

    int mb = wm * 64 + lm * 4;
    int nb = wn * 32 + ln * 4;

    float4 apre[ALD], wpre[WLD];
    int r_a[ALD], kq_a[ALD];
#pragma unroll
    for (int u = 0; u < ALD; u++) { int i = tid + 256 * u; r_a[u] = i >> 2; kq_a[u] = i & 3; }
    int r_w[WLD], kq_w[WLD];
#pragma unroll
    for (int u = 0; u < WLD; u++) { int i = tid + 256 * u; r_w[u] = i >> 2; kq_w[u] = i & 3; }

    int tiles = K / BK;
    unsigned long long accp[8][4];
#pragma unroll
    for (int i = 0; i < 8; i++)
#pragma unroll
        for (int jp = 0; jp < 4; jp++) accp[i][jp] = 0ull;

#pragma unroll
    for (int u = 0; u < ALD; u++)
        apre[u] = *(const float4*)(A + (size_t)(m0 + r_a[u]) * K + kq_a[u] * 4);
#pragma unroll
    for (int u = 0; u < WLD; u++)
        wpre[u] = *(const float4*)(W + (size_t)(n0 + r_w[u]) * K + kq_w[u] * 4);
    {
#pragma unroll
        for (int u = 0; u < ALD; u++) {
            float vals[4] = {apre[u].x, apre[u].y, apre[u].z, apre[u].w};
#pragma unroll
            for (int e = 0; e < 4; e++) {
                float v = vals[e];
                if (TRANS) {
                    int kk = kq_a[u] * 4 + e;
                    v = v * tsc[kk] + tsh[kk];
                    v = v >= 0.f ? v : SLOPE * v;
                }
                As[0][kq_a[u] * 4 + e][r_a[u]] = v;
            }
        }
#pragma unroll
        for (int u = 0; u < WLD; u++) {
            Ws[0][kq_w[u] * 4 + 0][r_w[u]] = wpre[u].x;
            Ws[0][kq_w[u] * 4 + 1][r_w[u]] = wpre[u].y;
            Ws[0][kq_w[u] * 4 + 2][r_w[u]] = wpre[u].z;
            Ws[0][kq_w[u] * 4 + 3][r_w[u]] = wpre[u].w;
        }
    }
    __syncthreads();

    for (int t = 0; t < tiles; t++) {
        int cur = t & 1, nxt = cur ^ 1;
        bool has_next = (t + 1) < tiles;
        if (has_next) {
            int k0 = (t + 1) * BK;
#pragma unroll
            for (int u = 0; u < ALD; u++)
                apre[u] = *(const float4*)(A + (size_t)(m0 + r_a[u]) * K + k0 + kq_a[u] * 4);
#pragma unroll
            for (int u = 0; u < WLD; u++)
                wpre[u] = *(const float4*)(W + (size_t)(n0 + r_w[u]) * K + k0 + kq_w[u] * 4);
        }
#pragma unroll
        for (int k = 0; k < BK; k++) {
            float4 a0 = *(const float4*)&As[cur][k][mb];
            float4 a1 = *(const float4*)&As[cur][k][mb + 32];
            ulonglong2 b0 = *(const ulonglong2*)&Ws[cur][k][nb];
            ulonglong2 b1 = *(const ulonglong2*)&Ws[cur][k][nb + 16];
            unsigned long long bp[4] = {b0.x, b0.y, b1.x, b1.y};
            float av[8] = {a0.x, a0.y, a0.z, a0.w, a1.x, a1.y, a1.z, a1.w};
#pragma unroll
            for (int i = 0; i < 8; i++) {
                unsigned long long ap = pack2b(av[i]);
#pragma unroll
                for (int jp = 0; jp < 4; jp++) ffma2(accp[i][jp], ap, bp[jp]);
            }
        }
        if (has_next) {
            int k0 = (t + 1) * BK;
#pragma unroll
            for (int u = 0; u < ALD; u++) {
                float vals[4] = {apre[u].x, apre[u].y, apre[u].z, apre[u].w};
#pragma unroll
                for (int e = 0; e < 4; e++) {
                    float v = vals[e];
                    if (TRANS) {
                        int kk = k0 + kq_a[u] * 4 + e;
                        v = v * tsc[kk] + tsh[kk];
                        v = v >= 0.f ? v : SLOPE * v;
                    }
                    As[nxt][kq_a[u] * 4 + e][r_a[u]] = v;
                }
            }
#pragma unroll
            for (int u = 0; u < WLD; u++) {
                Ws[nxt][kq_w[u] * 4 + 0][r_w[u]] = wpre[u].x;
                Ws[nxt][kq_w[u] * 4 + 1][r_w[u]] = wpre[u].y;
                Ws[nxt][kq_w[u] * 4 + 2][r_w[u]] = wpre[u].z;
                Ws[nxt][kq_w[u] * 4 + 3][r_w[u]] = wpre[u].w;
            }
        }
        __syncthreads();
    }

    float bia[8];
#pragma unroll
    for (int j = 0; j < 8; j++) {
        int n = n0 + nb + (j < 4 ? j : 12 + j);
        bia[j] = bias[n];
    }
    float s_j[8] = {}, q_j[8] = {};
    float runmax[8];
    int cur_pl = -1;
#pragma unroll
    for (int i = 0; i < 8; i++) {
        int mrow = mb + (i < 4 ? i : 28 + i);
        int m = m0 + mrow;
        float vrow[8];
        unpack2(accp[i][0], vrow[0], vrow[1]);
        unpack2(accp[i][1], vrow[2], vrow[3]);
        unpack2(accp[i][2], vrow[4], vrow[5]);
        unpack2(accp[i][3], vrow[6], vrow[7]);
#pragma unroll
        for (int j = 0; j < 8; j++) {
            float v = vrow[j] + bia[j];
            vrow[j] = v;
            s_j[j] += v;
            q_j[j] += v * v;
        }
        if (WRITE_C) {
            *(float4*)(C + (size_t)m * NN + n0 + nb) =
                make_float4(vrow[0], vrow[1], vrow[2], vrow[3]);
            *(float4*)(C + (size_t)m * NN + n0 + nb + 16) =
                make_float4(vrow[4], vrow[5], vrow[6], vrow[7]);
        }
        if (MAXF) {
            int pl = m / KNN - p_base;
            if (pl != cur_pl) {
                if (cur_pl >= 0) {
#pragma unroll
                    for (int j = 0; j < 8; j++) {
                        int c = nb + (j < 4 ? j : 12 + j);
                        atomicMax(&smax[cur_pl][c], fenc(runmax[j]));
                    }
                }
                cur_pl = pl;
#pragma unroll
                for (int j = 0; j < 8; j++) runmax[j] = vrow[j];
            } else {
#pragma unroll
                for (int j = 0; j < 8; j++) runmax[j] = fmaxf(runmax[j], vrow[j]);
            }
        }
    }
    if (MAXF && cur_pl >= 0) {
#pragma unroll
        for (int j = 0; j < 8; j++) {
            int c = nb + (j < 4 ? j : 12 + j);
            atomicMax(&smax[cur_pl][c], fenc(runmax[j]));
        }
    }
#pragma unroll
    for (int off = 1; off < 8; off <<= 1) {
#pragma unroll
        for (int j = 0; j < 8; j++) {
            s_j[j] += __shfl_xor_sync(0xffffffffu, s_j[j], off);
            q_j[j] += __shfl_xor_sync(0xffffffffu, q_j[j], off);
        }
    }
    __syncthreads();
    if (lm == 0) {
#pragma unroll
        for (int j = 0; j < 8; j++) {
            int c = nb + (j < 4 ? j : 12 + j);
            rs[wm][c] = s_j[j];
            rq[wm][c] = q_j[j];
        }
    }
    __syncthreads();
    for (int c = tid; c < BN; c += 256) {
        float s = 0.f, q = 0.f;
#pragma unroll
        for (int w = 0; w < WM; w++) { s += rs[w][c]; q += rq[w][c]; }
        ps[(size_t)blockIdx.y * NN + n0 + c] = s;
        pq[(size_t)blockIdx.y * NN + n0 + c] = q;
    }
    if (MAXF) {
        int npts = (m0 + BM - 1) / KNN - p_base + 1;
        for (int idx = tid; idx < npts * BN; idx += 256) {
            int pl = idx / BN, c = idx % BN;
            float v = fdec(smax[pl][c]);
            if (v > NEG_INF)
                amax_f(&cat[(size_t)(p_base + pl) * 512 + coff + n0 + c], v);
        }
    }
}

// ---------------- final ----------------
__global__ void final_kernel(float* __restrict__ out) {
    int i = blockIdx.x * 256 + threadIdx.x;
    int c = i & 1023;
    float v = g_sc[5][c] * g_t6[i] + g_sh[5][c];
    out[i] = v >= 0.f ? v : SLOPE * v;
}

// ---------------- launch ----------------
extern "C" void kernel_launch(void* const* d_in, const int* in_sizes, int n_in,
                              void* d_out, int out_size) {
    const float* x  = (const float*)d_in[0];
    const float* w1 = (const float*)d_in[1];
    const float* b1 = (const float*)d_in[2];
    const float* g1 = (const float*)d_in[3];
    const float* be1= (const float*)d_in[4];
    const float* w2 = (const float*)d_in[5];
    const float* b2 = (const float*)d_in[6];
    const float* g2 = (const float*)d_in[7];
    const float* be2= (const float*)d_in[8];
    const float* w3 = (const float*)d_in[9];
    const float* b3 = (const float*)d_in[10];
    const float* g3 = (const float*)d_in[11];
    const float* be3= (const float*)d_in[12];
    const float* w4 = (const float*)d_in[13];
    const float* b4 = (const float*)d_in[14];
    const float* g4 = (const float*)d_in[15];
    const float* be4= (const float*)d_in[16];
    const float* w5 = (const float*)d_in[17];
    const float* b5 = (const float*)d_in[18];
    const float* g5 = (const float*)d_in[19];
    const float* be5= (const float*)d_in[20];
    const float* w6 = (const float*)d_in[21];
    const float* b6 = (const float*)d_in[22];
    const float* g6 = (const float*)d_in[23];
    const float* be6= (const float*)d_in[24];
    float* out = (float*)d_out;

    float *t1, *t2, *t3, *t5, *t6, *cat, *scb, *shb, *csc, *csh, *ps, *pq;
    __nv_bfloat16 *w3h, *w3l, *w4h, *w4l, *w5h, *w5l, *w6h, *w6l;
    cudaGetSymbolAddress((void**)&t1, g_t1);
    cudaGetSymbolAddress((void**)&t2, g_t2);
    cudaGetSymbolAddress((void**)&t3, g_t3);
    cudaGetSymbolAddress((void**)&t5, g_t5);
    cudaGetSymbolAddress((void**)&t6, g_t6);
    cudaGetSymbolAddress((void**)&cat, g_cat);
    cudaGetSymbolAddress((void**)&scb, g_sc);
    cudaGetSymbolAddress((void**)&shb, g_sh);
    cudaGetSymbolAddress((void**)&csc, g_csc);
    cudaGetSymbolAddress((void**)&csh, g_csh);
    cudaGetSymbolAddress((void**)&ps, g_ps);
    cudaGetSymbolAddress((void**)&pq, g_pq);
    cudaGetSymbolAddress((void**)&w3h, g_w3h);
    cudaGetSymbolAddress((void**)&w3l, g_w3l);
    cudaGetSymbolAddress((void**)&w4h, g_w4h);
    cudaGetSymbolAddress((void**)&w4l, g_w4l);
    cudaGetSymbolAddress((void**)&w5h, g_w5h);
    cudaGetSymbolAddress((void**)&w5l, g_w5l);
    cudaGetSymbolAddress((void**)&w6h, g_w6h);
    cudaGetSymbolAddress((void**)&w6l, g_w6l);

    constexpr int SM64  = 128 * 132 * 4;       // 67584 > 4*16KB tiles
    constexpr int SM128 = 4 * 128 * 128 * 2;   // 131072 > Cb
    cudaFuncSetAttribute(mma_gemm_kernel<64,  true,  true >, cudaFuncAttributeMaxDynamicSharedMemorySize, SM64);
    cudaFuncSetAttribute(mma_gemm_kernel<128, false, true >, cudaFuncAttributeMaxDynamicSharedMemorySize, SM128);
    cudaFuncSetAttribute(mma_gemm_kernel<128, true,  false>, cudaFuncAttributeMaxDynamicSharedMemorySize, SM128);

    // init cat to -inf
    init_cat<<<P * 512 / 256, 256>>>(cat);

    // KNN
    xx_kernel<<<P / 256, 256>>>(x);
    pd_kernel<<<dim3(16, 16, Bb), 256>>>(x);
    topk_kernel<<<P / 16, 512>>>();

    // Weight splits (independent of KNN chain)
    wsplit_kernel<<<128 * 64 / 256, 256>>>(w3, w3h, w3l);
    wsplit_kernel<<<256 * 128 / 256, 256>>>(w4, w4h, w4l);
    wsplit_kernel<<<256 * 512 / 256, 256>>>(w5, w5h, w5l);
    wsplit_kernel<<<1024 * 256 / 256, 256>>>(w6, w6h, w6l);

    // Stage 1
    qp_kernel<<<dim3(16, Bb), 256>>>(x, w1);
    s1_kernel<<<P, 256>>>(b1, ps, pq, cat);
    stats_finalize<<<1, 256>>>(ps, pq, P, 64, (float)M4, 0, 0, g1, be1);

    // Stage 2 (FFMA2 path; small)
    gemm2_kernel<256, 64, true, true, true><<<dim3(1, M4 / 256), 256>>>(
        t1, w2, b2, scb + 0 * 1024, shb + 0 * 1024, t2, ps, pq, 64, 64, cat, 64);
    stats_finalize<<<1, 256>>>(ps, pq, M4 / 256, 64, (float)M4, 1, 64, g2, be2);

    // Stage 3: HMMA (K=64), writes t3 + x3 max
    mma_gemm_kernel<64, true, true><<<dim3(1, M4 / 128), 256, SM64>>>(
        t2, w3h, w3l, b3, scb + 1 * 1024, shb + 1 * 1024, t3, ps, pq, 64, 128, cat, 128);
    stats_finalize<<<2, 256>>>(ps, pq, M4 / 128, 128, (float)M4, 2, 128, g3, be3);

    // Stage 4: HMMA (K=128), no C write, x4 max
    mma_gemm_kernel<128, false, true><<<dim3(2, M4 / 128), 256, SM128>>>(
        t3, w4h, w4l, b4, scb + 2 * 1024, shb + 2 * 1024, nullptr, ps, pq, 128, 256, cat, 256);
    stats_finalize<<<4, 256>>>(ps, pq, M4 / 128, 256, (float)M4, 3, 256, g4, be4);

    // Stage 5: HMMA (K=512), cat -> t5 with csc/csh fold
    mma_gemm_kernel<128, true, false><<<dim3(2, P / 128), 256, SM128>>>(
        cat, w5h, w5l, b5, csc, csh, t5, ps, pq, 512, 256, nullptr, 0);
    stats_finalize<<<4, 256>>>(ps, pq, P / 128, 256, (float)P, 4, -1, g5, be5);

    // Stage 6: HMMA (K=256), t5 -> t6
    mma_gemm_kernel<128, true, false><<<dim3(8, P / 128), 256, SM128>>>(
        t5, w6h, w6l, b6, scb + 4 * 1024, shb + 4 * 1024, t6, ps, pq, 256, 1024, nullptr, 0);
    stats_finalize<<<16, 256>>>(ps, pq, P / 128, 1024, (float)P, 5, -1, g6, be6);

    // Final
    final_kernel<<<P * 1024 / 256, 256>>>(out);
}

// round 16
// speedup vs baseline: 1.3085x; 1.0173x over previous
#include <cuda_runtime.h>
#include <cuda_bf16.h>
#include <cstdint>
#include <math.h>

// ---------------- Problem constants ----------------
constexpr int Bb   = 8;
constexpr int Dd   = 60;
constexpr int NP   = 1024;
constexpr int KNN  = 20;
constexpr int P    = Bb * NP;        // 8192 points
constexpr int M4   = P * KNN;        // 163840 graph-feature rows
constexpr float EPSV  = 1e-5f;
constexpr float SLOPE = 0.2f;

#define NEG_INF (__int_as_float(0xff800000))

// exact float max via atomics (order-independent => deterministic)
__device__ __forceinline__ void amax_f(float* a, float v) {
    if (v >= 0.f) atomicMax((int*)a, __float_as_int(v));
    else          atomicMin((unsigned int*)a, __float_as_uint(v));
}

// ---------------- mma.sync helpers ----------------
__device__ __forceinline__ uint32_t smem_u32(const void* p) {
    uint32_t a;
    asm("{ .reg .u64 t; cvta.to.shared.u64 t, %1; cvt.u32.u64 %0, t; }" : "=r"(a) : "l"(p));
    return a;
}
__device__ __forceinline__ void ldsm4(uint32_t* r, uint32_t addr) {
    asm volatile("ldmatrix.sync.aligned.m8n8.x4.shared.b16 {%0,%1,%2,%3}, [%4];"
        : "=r"(r[0]), "=r"(r[1]), "=r"(r[2]), "=r"(r[3]) : "r"(addr));
}
__device__ __forceinline__ void mma16816(float* d, const uint32_t* a, const uint32_t* b) {
    asm volatile("mma.sync.aligned.m16n8k16.row.col.f32.bf16.bf16.f32 "
        "{%0,%1,%2,%3}, {%4,%5,%6,%7}, {%8,%9}, {%0,%1,%2,%3};"
        : "+f"(d[0]), "+f"(d[1]), "+f"(d[2]), "+f"(d[3])
        : "r"(a[0]), "r"(a[1]), "r"(a[2]), "r"(a[3]), "r"(b[0]), "r"(b[1]));
}
__device__ __forceinline__ void bf16split(float v, uint16_t& h, uint16_t& l) {
    __nv_bfloat16 hb = __float2bfloat16(v);
    __nv_bfloat16 lb = __float2bfloat16(v - __bfloat162float(hb));
    h = *(uint16_t*)&hb; l = *(uint16_t*)&lb;
}

// ---------------- Device scratch ----------------
__device__ float g_xx[P];
__device__ float g_pd[(size_t)Bb * NP * NP];
__device__ int   g_idx[M4];
__device__ float g_q[(size_t)P * 64];
__device__ float g_p[(size_t)P * 64];
__device__ float g_t2[(size_t)M4 * 64];
__device__ float g_t3[(size_t)M4 * 128];
__device__ float g_cat[(size_t)P * 512];
__device__ float g_t5[(size_t)P * 256];
__device__ float g_t6[(size_t)P * 1024];
__device__ float g_ps[1 << 20];
__device__ float g_pq[1 << 20];
__device__ float g_sc[6][1024];
__device__ float g_sh[6][1024];
__device__ float g_csc[512];
__device__ float g_csh[512];
__device__ __nv_bfloat16 g_w2h[64 * 64],    g_w2l[64 * 64];
__device__ __nv_bfloat16 g_w3h[128 * 64],   g_w3l[128 * 64];
__device__ __nv_bfloat16 g_w4h[256 * 128],  g_w4l[256 * 128];
__device__ __nv_bfloat16 g_w5h[256 * 512],  g_w5l[256 * 512];
__device__ __nv_bfloat16 g_w6h[1024 * 256], g_w6l[1024 * 256];

// ---------------- init cat to -inf ----------------
__global__ void init_cat(float* __restrict__ cat) {
    cat[blockIdx.x * 256 + threadIdx.x] = NEG_INF;
}

// ---------------- xx ----------------
__global__ void xx_kernel(const float* __restrict__ x) {
    int i = blockIdx.x * 256 + threadIdx.x;
    int b = i >> 10, n = i & 1023;
    const float* xb = x + (size_t)b * Dd * NP + n;
    float s = 0.f;
#pragma unroll
    for (int d = 0; d < Dd; d++) { float v = xb[d * NP]; s += v * v; }
    g_xx[i] = s;
}

// ---------------- pd ----------------
__global__ void pd_kernel(const float* __restrict__ x) {
    int b  = blockIdx.z;
    int n0 = blockIdx.y * 64;
    int m0 = blockIdx.x * 64;
    __shared__ float Xa[Dd][64];
    __shared__ float Xb[Dd][64];
    const float* xb = x + (size_t)b * Dd * NP;
    for (int l = threadIdx.x; l < Dd * 64; l += 256) {
        int d = l >> 6, mm = l & 63;
        Xa[d][mm] = xb[d * NP + n0 + mm];
        Xb[d][mm] = xb[d * NP + m0 + mm];
    }
    __syncthreads();
    int tx = threadIdx.x & 15, ty = threadIdx.x >> 4;
    float acc[4][4] = {};
#pragma unroll
    for (int d = 0; d < Dd; d++) {
        float a[4], c[4];
#pragma unroll
        for (int i = 0; i < 4; i++) a[i] = Xa[d][ty * 4 + i];
#pragma unroll
        for (int j = 0; j < 4; j++) c[j] = Xb[d][tx * 4 + j];
#pragma unroll
        for (int i = 0; i < 4; i++)
#pragma unroll
            for (int j = 0; j < 4; j++) acc[i][j] += a[i] * c[j];
    }
#pragma unroll
    for (int i = 0; i < 4; i++) {
        int n = n0 + ty * 4 + i;
        float xn = g_xx[b * NP + n];
#pragma unroll
        for (int j = 0; j < 4; j++) {
            int m = m0 + tx * 4 + j;
            g_pd[((size_t)b << 20) + (size_t)n * NP + m] =
                2.f * acc[i][j] - xn - g_xx[b * NP + m];
        }
    }
}

// ---------------- warp-per-row top-k ----------------
__global__ __launch_bounds__(512) void topk_kernel() {
    int warp = threadIdx.x >> 5, lane = threadIdx.x & 31;
    int bn = blockIdx.x * 16 + warp;
    const float* row = g_pd + (size_t)bn * NP;
    float v[32];
#pragma unroll
    for (int j = 0; j < 32; j++) v[j] = row[j * 32 + lane];
    float bv = v[0]; int bs = 0;
#pragma unroll
    for (int j = 1; j < 32; j++)
        if (v[j] > bv) { bv = v[j]; bs = j; }
    int* out = g_idx + bn * KNN;
    for (int it = 0; it < KNN; it++) {
        float rv = bv;
        int   ri = bs * 32 + lane;
#pragma unroll
        for (int off = 16; off > 0; off >>= 1) {
            float ov = __shfl_xor_sync(0xffffffffu, rv, off);
            int   oi = __shfl_xor_sync(0xffffffffu, ri, off);
            if (ov > rv || (ov == rv && oi < ri)) { rv = ov; ri = oi; }
        }
        if (lane == 0) out[it] = ri;
        if ((ri & 31) == lane) {
            v[ri >> 5] = NEG_INF;
            bv = v[0]; bs = 0;
#pragma unroll
            for (int j = 1; j < 32; j++)
                if (v[j] > bv) { bv = v[j]; bs = j; }
        }
    }
}

// ---------------- qp ----------------
__global__ void qp_kernel(const float* __restrict__ x, const float* __restrict__ w1) {
    int b  = blockIdx.y;
    int m0 = blockIdx.x * 64;
    __shared__ float xs[Dd][64];
    __shared__ float ws[64][120];
    const float* xb = x + (size_t)b * Dd * NP;
    for (int l = threadIdx.x; l < Dd * 64; l += 256) {
        int d = l >> 6, m = l & 63;
        xs[d][m] = xb[d * NP + m0 + m];
    }
    for (int l = threadIdx.x; l < 64 * 120; l += 256) ws[l / 120][l % 120] = w1[l];
    __syncthreads();
    int tx = threadIdx.x & 15, ty = threadIdx.x >> 4;
    float qa[4][4] = {}, pa[4][4] = {};
#pragma unroll
    for (int d = 0; d < Dd; d++) {
        float wa[4], wb[4], xm[4];
#pragma unroll
        for (int i = 0; i < 4; i++) {
            wa[i] = ws[ty * 4 + i][d];
            wb[i] = ws[ty * 4 + i][60 + d] - wa[i];
        }
#pragma unroll
        for (int j = 0; j < 4; j++) xm[j] = xs[d][tx * 4 + j];
#pragma unroll
        for (int i = 0; i < 4; i++)
#pragma unroll
            for (int j = 0; j < 4; j++) {
                qa[i][j] += wa[i] * xm[j];
                pa[i][j] += wb[i] * xm[j];
            }
    }
#pragma unroll
    for (int i = 0; i < 4; i++)
#pragma unroll
        for (int j = 0; j < 4; j++) {
            int o = ty * 4 + i, m = m0 + tx * 4 + j;
            size_t base = ((size_t)b * NP + m) * 64 + o;
            g_q[base] = qa[i][j];
            g_p[base] = pa[i][j];
        }
}

// ---------------- s1: stats + x1 raw max only (t1 never materialized) ----
__global__ __launch_bounds__(256) void s1_kernel(const float* __restrict__ b1,
                                                 float* __restrict__ ps,
                                                 float* __restrict__ pq,
                                                 float* __restrict__ cat) {
    int bn = blockIdx.x;
    int tid = threadIdx.x;
    int c = tid & 63, js = tid >> 6;
    int b = bn >> 10;
    float pv = g_p[(size_t)bn * 64 + c] + b1[c];
    int rbase = bn * KNN;
    float mx = NEG_INF, s = 0.f, q = 0.f;
#pragma unroll
    for (int jj = 0; jj < 5; jj++) {
        int row = rbase + js + jj * 4;
        int m = g_idx[row];
        float v = g_q[((size_t)(b << 10) + m) * 64 + c] + pv;
        mx = fmaxf(mx, v); s += v; q += v * v;
    }
    __shared__ float smx[4][64], ssm[4][64], sqm[4][64];
    smx[js][c] = mx; ssm[js][c] = s; sqm[js][c] = q;
    __syncthreads();
    if (js == 0) {
        float M = smx[0][c], S = ssm[0][c], Q = sqm[0][c];
#pragma unroll
        for (int k = 1; k < 4; k++) {
            M = fmaxf(M, smx[k][c]); S += ssm[k][c]; Q += sqm[k][c];
        }
        cat[(size_t)bn * 512 + c] = M;
        ps[(size_t)bn * 64 + c] = S;
        pq[(size_t)bn * 64 + c] = Q;
    }
}

// ---------------- stats finalize ----------------
__global__ void stats_finalize(const float* __restrict__ ps, const float* __restrict__ pq,
                               int nb, int O, float cnt, int stage, int coff,
                               const float* __restrict__ g, const float* __restrict__ be) {
    int c = blockIdx.x * 64 + (threadIdx.x & 63);
    int slot = threadIdx.x >> 6;
    double s = 0.0, q = 0.0;
    for (int i = slot; i < nb; i += 4) {
        s += ps[(size_t)i * O + c];
        q += pq[(size_t)i * O + c];
    }
    __shared__ double ds[4][64], dq[4][64];
    ds[slot][threadIdx.x & 63] = s;
    dq[slot][threadIdx.x & 63] = q;
    __syncthreads();
    if (slot == 0) {
        int t = threadIdx.x & 63;
        double S = ds[0][t], Q = dq[0][t];
#pragma unroll
        for (int k = 1; k < 4; k++) { S += ds[k][t]; Q += dq[k][t]; }
        double m = S / cnt;
        double v = Q / cnt - m * m;
        float a  = g[c] * rsqrtf((float)v + EPSV);
        float sh = be[c] - (float)m * a;
        g_sc[stage][c] = a;
        g_sh[stage][c] = sh;
        if (coff >= 0) { g_csc[coff + c] = a; g_csh[coff + c] = sh; }
    }
}

// ---------------- generic weight hi/lo bf16 split ----------------
__global__ void wsplit_kernel(const float* __restrict__ w,
                              __nv_bfloat16* __restrict__ dh,
                              __nv_bfloat16* __restrict__ dl) {
    int i = blockIdx.x * 256 + threadIdx.x;
    float v = w[i];
    __nv_bfloat16 h = __float2bfloat16(v);
    dh[i] = h;
    dl[i] = __float2bfloat16(v - __bfloat162float(h));
}

// =====================================================================
// s2_mma: stage-2 HMMA GEMM with FUSED GATHER (CTA 256m x 64n, K=64)
//   A row m = lrelu((q[b,idx[m]] + p[m/20])*sc1 + (sh1 + b1*sc1))
//   (FIX vs R14: q gather now includes the batch offset)
// =====================================================================
constexpr int S2_AH = 0;         // 32 KB (256 rows x 8 chunks x 16B)
constexpr int S2_AL = 32768;
constexpr int S2_BH = 65536;     // 8 KB
constexpr int S2_BL = 73728;
constexpr int S2_SMEM = 81920;

__global__ __launch_bounds__(256, 1) void s2_mma_kernel(
    const __nv_bfloat16* __restrict__ Wh, const __nv_bfloat16* __restrict__ Wl,
    const float* __restrict__ b1, const float* __restrict__ bias,
    const float* __restrict__ tsc, const float* __restrict__ tsh,
    float* __restrict__ C, float* __restrict__ ps, float* __restrict__ pq,
    float* __restrict__ cat) {
    extern __shared__ char smem[];
    uint32_t sb = smem_u32(smem);
    int tid = threadIdx.x, lane = tid & 31, warp = tid >> 5;
    int m0 = blockIdx.x * 256;

    __shared__ float esc[64], esh[64];
    if (tid < 64) {
        float sc = tsc[tid];
        esc[tid] = sc;
        esh[tid] = tsh[tid] + b1[tid] * sc;
    }
    __syncthreads();

    // ---- A: gather q+p, BN1+lrelu, hi/lo split, swizzled store ----
#pragma unroll
    for (int i = 0; i < 8; i++) {
        int idx = tid + 256 * i;                   // 2048 chunks
        int r = idx >> 3, c = idx & 7;
        int m = m0 + r;
        int b = m / (NP * KNN);                    // batch of this row
        int gi = g_idx[m];                         // within-batch neighbor idx
        int pn = m / KNN;                          // global point id
        const float* qa = g_q + ((size_t)(b << 10) + gi) * 64 + c * 8;   // FIX
        const float* pa = g_p + (size_t)pn * 64 + c * 8;
        float4 q0 = *(const float4*)qa, q1 = *(const float4*)(qa + 4);
        float4 p0 = *(const float4*)pa, p1 = *(const float4*)(pa + 4);
        float vv[8] = {q0.x + p0.x, q0.y + p0.y, q0.z + p0.z, q0.w + p0.w,
                       q1.x + p1.x, q1.y + p1.y, q1.z + p1.z, q1.w + p1.w};
        uint32_t hp[4], lp[4];
#pragma unroll
        for (int e = 0; e < 4; e++) {
            uint32_t hw = 0, lw = 0;
#pragma unroll
            for (int t = 0; t < 2; t++) {
                int k = c * 8 + e * 2 + t;
                float v = vv[e * 2 + t] * esc[k] + esh[k];
                v = v >= 0.f ? v : SLOPE * v;
                uint16_t h, l;
                bf16split(v, h, l);
                hw |= (uint32_t)h << (16 * t);
                lw |= (uint32_t)l << (16 * t);
            }
            hp[e] = hw; lp[e] = lw;
        }
        int dst = (r * 8 + (c ^ (r & 7))) * 16;
        *(uint4*)(smem + S2_AH + dst) = make_uint4(hp[0], hp[1], hp[2], hp[3]);
        *(uint4*)(smem + S2_AL + dst) = make_uint4(lp[0], lp[1], lp[2], lp[3]);
    }
    // ---- B: copy pre-split bf16, swizzled ----
#pragma unroll
    for (int i = 0; i < 2; i++) {
        int idx = tid + 256 * i;                   // 512 chunks
        int r = idx >> 3, c = idx & 7;
        uint4 hv = *(const uint4*)(Wh + (size_t)r * 64 + c * 8);
        uint4 lv = *(const uint4*)(Wl + (size_t)r * 64 + c * 8);
        int dst = (r * 8 + (c ^ (r & 7))) * 16;
        *(uint4*)(smem + S2_BH + dst) = hv;
        *(uint4*)(smem + S2_BL + dst) = lv;
    }
    __syncthreads();

    int aRow0 = warp * 32 + (lane & 15);
    int aKsel = lane >> 4;
    int bRow0 = (lane & 7) + ((lane >> 4) << 3);
    int bKsel = (lane >> 3) & 1;

    float acc[2][8][4];
#pragma unroll
    for (int a = 0; a < 2; a++)
#pragma unroll
        for (int b = 0; b < 8; b++)
#pragma unroll
            for (int d = 0; d < 4; d++) acc[a][b][d] = 0.f;

#pragma unroll
    for (int ks = 0; ks < 4; ks++) {
        uint32_t aHr[2][4], aLr[2][4], bHr[16], bLr[16];
#pragma unroll
        for (int mt = 0; mt < 2; mt++) {
            int row = aRow0 + mt * 16;
            int ch = (ks * 2 + aKsel) ^ (row & 7);
            uint32_t off = (uint32_t)(row * 8 + ch) * 16;
            ldsm4(aHr[mt], sb + S2_AH + off);
            ldsm4(aLr[mt], sb + S2_AL + off);
        }
#pragma unroll
        for (int bt = 0; bt < 4; bt++) {
            int row = bRow0 + bt * 16;
            int ch = (ks * 2 + bKsel) ^ (row & 7);
            uint32_t off = (uint32_t)(row * 8 + ch) * 16;
            ldsm4(&bHr[bt * 4], sb + S2_BH + off);
            ldsm4(&bLr[bt * 4], sb + S2_BL + off);
        }
#pragma unroll
        for (int mt = 0; mt < 2; mt++)
#pragma unroll
            for (int j = 0; j < 8; j++) {
                const uint32_t* bh = &bHr[(j >> 1) * 4 + (j & 1) * 2];
                const uint32_t* bl = &bLr[(j >> 1) * 4 + (j & 1) * 2];
                mma16816(acc[mt][j], aHr[mt], bh);
                mma16816(acc[mt][j], aHr[mt], bl);
                mma16816(acc[mt][j], aLr[mt], bh);
            }
    }
    __syncthreads();

    // ---- C tile -> smem [256][68], add bias ----
    float* Cb = (float*)smem;
    int gr = lane >> 2, tg = lane & 3;
#pragma unroll
    for (int mt = 0; mt < 2; mt++) {
        int r0 = warp * 32 + mt * 16 + gr;
#pragma unroll
        for (int j = 0; j < 8; j++) {
            int col = j * 8 + tg * 2;
            float b0 = bias[col], b1v = bias[col + 1];
            Cb[r0 * 68 + col]           = acc[mt][j][0] + b0;
            Cb[r0 * 68 + col + 1]       = acc[mt][j][1] + b1v;
            Cb[(r0 + 8) * 68 + col]     = acc[mt][j][2] + b0;
            Cb[(r0 + 8) * 68 + col + 1] = acc[mt][j][3] + b1v;
        }
    }
    __syncthreads();

    // write t2
    for (int idx = tid; idx < 256 * 16; idx += 256) {
        int r = idx >> 4, c4 = idx & 15;
        *(float4*)(C + (size_t)(m0 + r) * 64 + c4 * 4) = *(float4*)&Cb[r * 68 + c4 * 4];
    }
    // per-channel partial stats
    __shared__ float sps[4][64], spq[4][64];
    {
        int j = tid & 63, qrt = tid >> 6;
        float s = 0.f, q = 0.f;
        for (int r = qrt * 64; r < qrt * 64 + 64; r++) {
            float v = Cb[r * 68 + j];
            s += v; q += v * v;
        }
        sps[qrt][j] = s; spq[qrt][j] = q;
    }
    __syncthreads();
    if (tid < 64) {
        ps[(size_t)blockIdx.x * 64 + tid] = sps[0][tid] + sps[1][tid] + sps[2][tid] + sps[3][tid];
        pq[(size_t)blockIdx.x * 64 + tid] = spq[0][tid] + spq[1][tid] + spq[2][tid] + spq[3][tid];
    }
    // per-point raw max -> cat (x2 slot, coff=64)
    int p_first = m0 / KNN;
    int p_last  = (m0 + 255) / KNN;
    int npts = p_last - p_first + 1;
    for (int it = tid; it < npts * 64; it += 256) {
        int pl = it >> 6, j = it & 63;
        int p = p_first + pl;
        int r0 = max(p * KNN - m0, 0);
        int r1 = min(p * KNN + KNN - m0, 256);
        float mx = NEG_INF;
        for (int r = r0; r < r1; r++) mx = fmaxf(mx, Cb[r * 68 + j]);
        if (r1 > r0) amax_f(&cat[(size_t)p * 512 + 64 + j], mx);
    }
}

// =====================================================================
// mma_gemm: generalized bf16-split HMMA GEMM (CTA 128m x 128n, K-chunked)
// =====================================================================
template <int KC, bool WRITE_C, bool MAXF>
__global__ __launch_bounds__(256, 1) void mma_gemm_kernel(
    const float* __restrict__ A, const __nv_bfloat16* __restrict__ Wh,
    const __nv_bfloat16* __restrict__ Wl, const float* __restrict__ bias,
    const float* __restrict__ tsc, const float* __restrict__ tsh,
    float* __restrict__ C, float* __restrict__ ps, float* __restrict__ pq,
    int K, int NN, float* __restrict__ cat, int coff) {
    constexpr int CH = KC / 8;
    constexpr int TILE = 128 * CH * 16;
    extern __shared__ char smem[];
    uint32_t sb = smem_u32(smem);
    const int AH = 0, AL = TILE, BH = 2 * TILE, BL = 3 * TILE;

    int tid = threadIdx.x;
    int lane = tid & 31, warp = tid >> 5;
    int wm = warp & 3, wn = warp >> 2;
    int m0 = blockIdx.y * 128;
    int n0 = blockIdx.x * 128;

    int aRow0 = wm * 32 + (lane & 15);
    int aKsel = lane >> 4;
    int bRow0 = wn * 64 + (lane & 7) + ((lane >> 4) << 3);
    int bKsel = (lane >> 3) & 1;

    float acc[2][8][4];
#pragma unroll
    for (int a = 0; a < 2; a++)
#pragma unroll
        for (int b = 0; b < 8; b++)
#pragma unroll
            for (int d = 0; d < 4; d++) acc[a][b][d] = 0.f;

    for (int k0 = 0; k0 < K; k0 += KC) {
        if (k0 > 0) __syncthreads();
#pragma unroll
        for (int i = 0; i < CH / 2; i++) {
            int idx = tid + 256 * i;
            int r = idx / CH, c = idx % CH;
            const float* src = A + (size_t)(m0 + r) * K + k0 + c * 8;
            float4 v0 = *(const float4*)(src);
            float4 v1 = *(const float4*)(src + 4);
            float vv[8] = {v0.x, v0.y, v0.z, v0.w, v1.x, v1.y, v1.z, v1.w};
            uint32_t hp[4], lp[4];
#pragma unroll
            for (int e = 0; e < 4; e++) {
                uint32_t hw = 0, lw = 0;
#pragma unroll
                for (int t = 0; t < 2; t++) {
                    int k = k0 + c * 8 + e * 2 + t;
                    float v = vv[e * 2 + t] * tsc[k] + tsh[k];
                    v = v >= 0.f ? v : SLOPE * v;
                    uint16_t h, l;
                    bf16split(v, h, l);
                    hw |= (uint32_t)h << (16 * t);
                    lw |= (uint32_t)l << (16 * t);
                }
                hp[e] = hw; lp[e] = lw;
            }
            int dst = (r * CH + (c ^ (r & 7))) * 16;
            *(uint4*)(smem + AH + dst) = make_uint4(hp[0], hp[1], hp[2], hp[3]);
            *(uint4*)(smem + AL + dst) = make_uint4(lp[0], lp[1], lp[2], lp[3]);
        }
#pragma unroll
        for (int i = 0; i < CH / 2; i++) {
            int idx = tid + 256 * i;
            int r = idx / CH, c = idx % CH;
            uint4 hv = *(const uint4*)(Wh + (size_t)(n0 + r) * K + k0 + c * 8);
            uint4 lv = *(const uint4*)(Wl + (size_t)(n0 + r) * K + k0 + c * 8);
            int dst = (r * CH + (c ^ (r & 7))) * 16;
            *(uint4*)(smem + BH + dst) = hv;
            *(uint4*)(smem + BL + dst) = lv;
        }
        __syncthreads();

#pragma unroll
        for (int ks = 0; ks < KC / 16; ks++) {
            uint32_t aHr[2][4], aLr[2][4], bHr[16], bLr[16];
#pragma unroll
            for (int mt = 0; mt < 2; mt++) {
                int row = aRow0 + mt * 16;
                int ch = (ks * 2 + aKsel) ^ (row & 7);
                uint32_t off = (uint32_t)(row * CH + ch) * 16;
                ldsm4(aHr[mt], sb + AH + off);
                ldsm4(aLr[mt], sb + AL + off);
            }
#pragma unroll
            for (int bt = 0; bt < 4; bt++) {
                int row = bRow0 + bt * 16;
                int ch = (ks * 2 + bKsel) ^ (row & 7);
                uint32_t off = (uint32_t)(row * CH + ch) * 16;
                ldsm4(&bHr[bt * 4], sb + BH + off);
                ldsm4(&bLr[bt * 4], sb + BL + off);
            }
#pragma unroll
            for (int mt = 0; mt < 2; mt++)
#pragma unroll
                for (int j = 0; j < 8; j++) {
                    const uint32_t* bh = &bHr[(j >> 1) * 4 + (j & 1) * 2];
                    const uint32_t* bl = &bLr[(j >> 1) * 4 + (j & 1) * 2];
                    mma16816(acc[mt][j], aHr[mt], bh);
                    mma16816(acc[mt][j], aHr[mt], bl);
                    mma16816(acc[mt][j], aLr[mt], bh);
                }
        }
    }
    __syncthreads();

    float* Cb = (float*)smem;                  // [128][132]
    int gr = lane >> 2, tg = lane & 3;
#pragma unroll
    for (int mt = 0; mt < 2; mt++) {
        int r0 = wm * 32 + mt * 16 + gr;
#pragma unroll
        for (int j = 0; j < 8; j++) {
            int col = wn * 64 + j * 8 + tg * 2;
            float b0 = bias[n0 + col], b1 = bias[n0 + col + 1];
            Cb[r0 * 132 + col]           = acc[mt][j][0] + b0;
            Cb[r0 * 132 + col + 1]       = acc[mt][j][1] + b1;
            Cb[(r0 + 8) * 132 + col]     = acc[mt][j][2] + b0;
            Cb[(r0 + 8) * 132 + col + 1] = acc[mt][j][3] + b1;
        }
    }
    __syncthreads();

    if (WRITE_C) {
        for (int idx = tid; idx < 128 * 32; idx += 256) {
            int r = idx >> 5, c4 = idx & 31;
            float4 v = *(float4*)&Cb[r * 132 + c4 * 4];
            *(float4*)(C + (size_t)(m0 + r) * NN + n0 + c4 * 4) = v;
        }
    }
    __shared__ float sps[2][128], spq[2][128];
    {
        int j = tid & 127, h = tid >> 7;
        float s = 0.f, q = 0.f;
        for (int r = h * 64; r < h * 64 + 64; r++) {
            float v = Cb[r * 132 + j];
            s += v; q += v * v;
        }
        sps[h][j] = s; spq[h][j] = q;
    }
    __syncthreads();
    if (tid < 128) {
        ps[(size_t)blockIdx.y * NN + n0 + tid] = sps[0][tid] + sps[1][tid];
        pq[(size_t)blockIdx.y * NN + n0 + tid] = spq[0][tid] + spq[1][tid];
    }
    if (MAXF) {
        int p_first = m0 / KNN;
        int p_last  = (m0 + 127) / KNN;
        int npts = p_last - p_first + 1;
        for (int it = tid; it < npts * 128; it += 256) {
            int pl = it >> 7, j = it & 127;
            int p = p_first + pl;
            int r0 = max(p * KNN - m0, 0);
            int r1 = min(p * KNN + KNN - m0, 128);
            float mx = NEG_INF;
            for (int r = r0; r < r1; r++) mx = fmaxf(mx, Cb[r * 132 + j]);
            if (r1 > r0) amax_f(&cat[(size_t)p * 512 + coff + n0 + j], mx);
        }
    }
}

// ---------------- final ----------------
__global__ void final_kernel(float* __restrict__ out) {
    int i = blockIdx.x * 256 + threadIdx.x;
    int c = i & 1023;
    float v = g_sc[5][c] * g_t6[i] + g_sh[5][c];
    out[i] = v >= 0.f ? v : SLOPE * v;
}

// ---------------- launch ----------------
extern "C" void kernel_launch(void* const* d_in, const int* in_sizes, int n_in,
                              void* d_out, int out_size) {
    const float* x  = (const float*)d_in[0];
    const float* w1 = (const float*)d_in[1];
    const float* b1 = (const float*)d_in[2];
    const float* g1 = (const float*)d_in[3];
    const float* be1= (const float*)d_in[4];
    const float* w2 = (const float*)d_in[5];
    const float* b2 = (const float*)d_in[6];
    const float* g2 = (const float*)d_in[7];
    const float* be2= (const float*)d_in[8];
    const float* w3 = (const float*)d_in[9];
    const float* b3 = (const float*)d_in[10];
    const float* g3 = (const float*)d_in[11];
    const float* be3= (const float*)d_in[12];
    const float* w4 = (const float*)d_in[13];
    const float* b4 = (const float*)d_in[14];
    const float* g4 = (const float*)d_in[15];
    const float* be4= (const float*)d_in[16];
    const float* w5 = (const float*)d_in[17];
    const float* b5 = (const float*)d_in[18];
    const float* g5 = (const float*)d_in[19];
    const float* be5= (const float*)d_in[20];
    const float* w6 = (const float*)d_in[21];
    const float* b6 = (const float*)d_in[22];
    const float* g6 = (const float*)d_in[23];
    const float* be6= (const float*)d_in[24];
    float* out = (float*)d_out;

    float *t2, *t3, *t5, *t6, *cat, *scb, *shb, *csc, *csh, *ps, *pq;
    __nv_bfloat16 *w2h, *w2l, *w3h, *w3l, *w4h, *w4l, *w5h, *w5l, *w6h, *w6l;
    cudaGetSymbolAddress((void**)&t2, g_t2);
    cudaGetSymbolAddress((void**)&t3, g_t3);
    cudaGetSymbolAddress((void**)&t5, g_t5);
    cudaGetSymbolAddress((void**)&t6, g_t6);
    cudaGetSymbolAddress((void**)&cat, g_cat);
    cudaGetSymbolAddress((void**)&scb, g_sc);
    cudaGetSymbolAddress((void**)&shb, g_sh);
    cudaGetSymbolAddress((void**)&csc, g_csc);
    cudaGetSymbolAddress((void**)&csh, g_csh);
    cudaGetSymbolAddress((void**)&ps, g_ps);
    cudaGetSymbolAddress((void**)&pq, g_pq);
    cudaGetSymbolAddress((void**)&w2h, g_w2h);
    cudaGetSymbolAddress((void**)&w2l, g_w2l);
    cudaGetSymbolAddress((void**)&w3h, g_w3h);
    cudaGetSymbolAddress((void**)&w3l, g_w3l);
    cudaGetSymbolAddress((void**)&w4h, g_w4h);
    cudaGetSymbolAddress((void**)&w4l, g_w4l);
    cudaGetSymbolAddress((void**)&w5h, g_w5h);
    cudaGetSymbolAddress((void**)&w5l, g_w5l);
    cudaGetSymbolAddress((void**)&w6h, g_w6h);
    cudaGetSymbolAddress((void**)&w6l, g_w6l);

    constexpr int SM64  = 128 * 132 * 4;
    constexpr int SM128 = 4 * 128 * 128 * 2;
    cudaFuncSetAttribute(s2_mma_kernel, cudaFuncAttributeMaxDynamicSharedMemorySize, S2_SMEM);
    cudaFuncSetAttribute(mma_gemm_kernel<64,  true,  true >, cudaFuncAttributeMaxDynamicSharedMemorySize, SM64);
    cudaFuncSetAttribute(mma_gemm_kernel<128, false, true >, cudaFuncAttributeMaxDynamicSharedMemorySize, SM128);
    cudaFuncSetAttribute(mma_gemm_kernel<128, true,  false>, cudaFuncAttributeMaxDynamicSharedMemorySize, SM128);

    // init cat to -inf
    init_cat<<<P * 512 / 256, 256>>>(cat);

    // KNN
    xx_kernel<<<P / 256, 256>>>(x);
    pd_kernel<<<dim3(16, 16, Bb), 256>>>(x);
    topk_kernel<<<P / 16, 512>>>();

    // Weight splits (independent of KNN chain)
    wsplit_kernel<<<64 * 64 / 256, 256>>>(w2, w2h, w2l);
    wsplit_kernel<<<128 * 64 / 256, 256>>>(w3, w3h, w3l);
    wsplit_kernel<<<256 * 128 / 256, 256>>>(w4, w4h, w4l);
    wsplit_kernel<<<256 * 512 / 256, 256>>>(w5, w5h, w5l);
    wsplit_kernel<<<1024 * 256 / 256, 256>>>(w6, w6h, w6l);

    // Stage 1: stats + x1 max (t1 virtual)
    qp_kernel<<<dim3(16, Bb), 256>>>(x, w1);
    s1_kernel<<<P, 256>>>(b1, ps, pq, cat);
    stats_finalize<<<1, 256>>>(ps, pq, P, 64, (float)M4, 0, 0, g1, be1);

    // Stage 2: HMMA with fused gather (t1 never materialized)
    s2_mma_kernel<<<M4 / 256, 256, S2_SMEM>>>(
        w2h, w2l, b1, b2, scb + 0 * 1024, shb + 0 * 1024, t2, ps, pq, cat);
    stats_finalize<<<1, 256>>>(ps, pq, M4 / 256, 64, (float)M4, 1, 64, g2, be2);

    // Stage 3: HMMA (K=64), writes t3 + x3 max
    mma_gemm_kernel<64, true, true><<<dim3(1, M4 / 128), 256, SM64>>>(
        t2, w3h, w3l, b3, scb + 1 * 1024, shb + 1 * 1024, t3, ps, pq, 64, 128, cat, 128);
    stats_finalize<<<2, 256>>>(ps, pq, M4 / 128, 128, (float)M4, 2, 128, g3, be3);

    // Stage 4: HMMA (K=128), no C write, x4 max
    mma_gemm_kernel<128, false, true><<<dim3(2, M4 / 128), 256, SM128>>>(
        t3, w4h, w4l, b4, scb + 2 * 1024, shb + 2 * 1024, nullptr, ps, pq, 128, 256, cat, 256);
    stats_finalize<<<4, 256>>>(ps, pq, M4 / 128, 256, (float)M4, 3, 256, g4, be4);

    // Stage 5: HMMA (K=512), cat -> t5 with csc/csh fold
    mma_gemm_kernel<128, true, false><<<dim3(2, P / 128), 256, SM128>>>(
        cat, w5h, w5l, b5, csc, csh, t5, ps, pq, 512, 256, nullptr, 0);
    stats_finalize<<<4, 256>>>(ps, pq, P / 128, 256, (float)P, 4, -1, g5, be5);

    // Stage 6: HMMA (K=256), t5 -> t6
    mma_gemm_kernel<128, true, false><<<dim3(8, P / 128), 256, SM128>>>(
        t5, w6h, w6l, b6, scb + 4 * 1024, shb + 4 * 1024, t6, ps, pq, 256, 1024, nullptr, 0);
    stats_finalize<<<16, 256>>>(ps, pq, P / 128, 1024, (float)P, 5, -1, g6, be6);

    // Final
    final_kernel<<<P * 1024 / 256, 256>>>(out);
}